// round 1
// baseline (speedup 1.0000x reference)
#include <cuda_runtime.h>
#include <math.h>

// Problem constants
#define BB 2
#define SS 2048
#define DD 1024
#define HH 16
#define DK 64
#define MROWS (BB * SS)   // 4096

// Scratch (alloc-free rule: __device__ globals)
__device__ float g_q[BB * SS * DD];
__device__ float g_k[BB * SS * DD];
__device__ float g_v[BB * SS * DD];
__device__ float g_x[BB * SS * DD];

// ---------------------------------------------------------------------------
// GEMM: C[M,N] = A[M,K] * W[N,K]^T + bias[N]
// 128x128 tile, BK=8, 256 threads, 8x8 per thread (split 4+4 rows/cols).
// ---------------------------------------------------------------------------
__global__ __launch_bounds__(256) void gemm_nt(
    const float* __restrict__ A, const float* __restrict__ W,
    const float* __restrict__ bias, float* __restrict__ C,
    int M, int N, int K)
{
    __shared__ float As[8][128];
    __shared__ float Ws[8][128];

    const int t = threadIdx.x;
    const int m0 = blockIdx.y * 128;
    const int n0 = blockIdx.x * 128;
    const int lrow = t >> 1;          // 0..127
    const int lk = (t & 1) * 4;       // 0 or 4
    const int tx = t & 15;
    const int ty = t >> 4;

    const float* Ap = A + (size_t)(m0 + lrow) * K + lk;
    const float* Wp = W + (size_t)(n0 + lrow) * K + lk;

    float acc[8][8];
#pragma unroll
    for (int i = 0; i < 8; i++)
#pragma unroll
        for (int j = 0; j < 8; j++) acc[i][j] = 0.0f;

    for (int k0 = 0; k0 < K; k0 += 8) {
        float4 av = *(const float4*)(Ap + k0);
        float4 wv = *(const float4*)(Wp + k0);
        __syncthreads();
        As[lk + 0][lrow] = av.x; As[lk + 1][lrow] = av.y;
        As[lk + 2][lrow] = av.z; As[lk + 3][lrow] = av.w;
        Ws[lk + 0][lrow] = wv.x; Ws[lk + 1][lrow] = wv.y;
        Ws[lk + 2][lrow] = wv.z; Ws[lk + 3][lrow] = wv.w;
        __syncthreads();
#pragma unroll
        for (int kk = 0; kk < 8; kk++) {
            float a[8], b[8];
            *(float4*)&a[0] = *(const float4*)&As[kk][4 * ty];
            *(float4*)&a[4] = *(const float4*)&As[kk][64 + 4 * ty];
            *(float4*)&b[0] = *(const float4*)&Ws[kk][4 * tx];
            *(float4*)&b[4] = *(const float4*)&Ws[kk][64 + 4 * tx];
#pragma unroll
            for (int i = 0; i < 8; i++)
#pragma unroll
                for (int j = 0; j < 8; j++) acc[i][j] += a[i] * b[j];
        }
    }

#pragma unroll
    for (int hi = 0; hi < 2; hi++) {
#pragma unroll
        for (int i2 = 0; i2 < 4; i2++) {
            const int row = m0 + hi * 64 + 4 * ty + i2;
            const int i = hi * 4 + i2;
#pragma unroll
            for (int hj = 0; hj < 2; hj++) {
                const int col = n0 + hj * 64 + 4 * tx;
                float4 bv = *(const float4*)&bias[col];
                float4 r;
                r.x = acc[i][hj * 4 + 0] + bv.x;
                r.y = acc[i][hj * 4 + 1] + bv.y;
                r.z = acc[i][hj * 4 + 2] + bv.z;
                r.w = acc[i][hj * 4 + 3] + bv.w;
                *(float4*)&C[(size_t)row * N + col] = r;
            }
        }
    }
}

// ---------------------------------------------------------------------------
// Flash attention: one block per (b, h, 64-row q tile). 256 threads (16x16),
// each thread owns a 4x4 score micro-tile. Online softmax; numerator carries
// group_prob, denominator does not (matches post-softmax scaling).
// smem: Qt (d-major), KtPs (K d-major, reused as P row-major), Vs (k-major).
// ---------------------------------------------------------------------------
__global__ __launch_bounds__(256) void attn_kernel(
    const float* __restrict__ Qp, const float* __restrict__ Kp,
    const float* __restrict__ Vp, const float* __restrict__ Gp,
    const int* __restrict__ Mp, float* __restrict__ Op)
{
    __shared__ float Qt[64 * 64];
    __shared__ float KtPs[64 * 64];
    __shared__ float Vs[64 * 64];

    const int b = blockIdx.z, h = blockIdx.y;
    const int q0 = blockIdx.x * 64;
    const int t = threadIdx.x;
    const int tx = t & 15, ty = t >> 4;
    const int lr = t >> 2, ld0 = (t & 3) * 16;

    // load Q tile transposed (d-major)
    {
        const float* Qb = Qp + (size_t)(b * SS + q0 + lr) * DD + h * DK + ld0;
#pragma unroll
        for (int i = 0; i < 4; i++) {
            float4 v = *(const float4*)(Qb + 4 * i);
            Qt[(ld0 + 4 * i + 0) * 64 + lr] = v.x;
            Qt[(ld0 + 4 * i + 1) * 64 + lr] = v.y;
            Qt[(ld0 + 4 * i + 2) * 64 + lr] = v.z;
            Qt[(ld0 + 4 * i + 3) * 64 + lr] = v.w;
        }
    }

    float m_run[4], l_run[4], Oacc[4][4];
#pragma unroll
    for (int i = 0; i < 4; i++) {
        m_run[i] = -1e30f;
        l_run[i] = 0.0f;
#pragma unroll
        for (int j = 0; j < 4; j++) Oacc[i][j] = 0.0f;
    }

    for (int k0 = 0; k0 < SS; k0 += 64) {
        __syncthreads();  // prior PV done with KtPs/Vs
        // load K (transposed, d-major) and V (natural, k-major)
        {
            const float* Kb = Kp + (size_t)(b * SS + k0 + lr) * DD + h * DK + ld0;
            const float* Vb = Vp + (size_t)(b * SS + k0 + lr) * DD + h * DK + ld0;
#pragma unroll
            for (int i = 0; i < 4; i++) {
                float4 kv = *(const float4*)(Kb + 4 * i);
                KtPs[(ld0 + 4 * i + 0) * 64 + lr] = kv.x;
                KtPs[(ld0 + 4 * i + 1) * 64 + lr] = kv.y;
                KtPs[(ld0 + 4 * i + 2) * 64 + lr] = kv.z;
                KtPs[(ld0 + 4 * i + 3) * 64 + lr] = kv.w;
                float4 vv = *(const float4*)(Vb + 4 * i);
                *(float4*)&Vs[lr * 64 + ld0 + 4 * i] = vv;
            }
        }
        int mk[4];
#pragma unroll
        for (int j = 0; j < 4; j++) mk[j] = Mp[b * SS + k0 + 4 * tx + j];
        __syncthreads();

        // S = Q K^T for this thread's 4x4 micro-tile
        float Sv[4][4];
#pragma unroll
        for (int i = 0; i < 4; i++)
#pragma unroll
            for (int j = 0; j < 4; j++) Sv[i][j] = 0.0f;
#pragma unroll 8
        for (int d = 0; d < 64; d++) {
            float4 qa = *(const float4*)&Qt[d * 64 + 4 * ty];
            float4 kb = *(const float4*)&KtPs[d * 64 + 4 * tx];
            float a[4] = {qa.x, qa.y, qa.z, qa.w};
            float bl[4] = {kb.x, kb.y, kb.z, kb.w};
#pragma unroll
            for (int i = 0; i < 4; i++)
#pragma unroll
                for (int j = 0; j < 4; j++) Sv[i][j] += a[i] * bl[j];
        }
        __syncthreads();  // done reading K before P overwrites the buffer

        // scale + mask + online softmax stats
        const float scale = 0.125f;  // 1/sqrt(64)
        float mt[4];
#pragma unroll
        for (int i = 0; i < 4; i++) {
            const int rowq = q0 + 4 * ty + i;
#pragma unroll
            for (int j = 0; j < 4; j++) {
                float s = Sv[i][j] * scale;
                const int colk = k0 + 4 * tx + j;
                if (mk[j] == 0 && colk != rowq) s = -1e9f;
                Sv[i][j] = s;
            }
            mt[i] = fmaxf(fmaxf(Sv[i][0], Sv[i][1]), fmaxf(Sv[i][2], Sv[i][3]));
        }
#pragma unroll
        for (int off = 1; off < 16; off <<= 1)
#pragma unroll
            for (int i = 0; i < 4; i++)
                mt[i] = fmaxf(mt[i], __shfl_xor_sync(0xffffffffu, mt[i], off));

        float c[4], rs[4];
#pragma unroll
        for (int i = 0; i < 4; i++) {
            float m_new = fmaxf(m_run[i], mt[i]);
            c[i] = __expf(m_run[i] - m_new);
            m_run[i] = m_new;
            rs[i] = 0.0f;
#pragma unroll
            for (int j = 0; j < 4; j++) {
                float p = __expf(Sv[i][j] - m_new);
                Sv[i][j] = p;
                rs[i] += p;
            }
        }
#pragma unroll
        for (int off = 1; off < 16; off <<= 1)
#pragma unroll
            for (int i = 0; i < 4; i++)
                rs[i] += __shfl_xor_sync(0xffffffffu, rs[i], off);
#pragma unroll
        for (int i = 0; i < 4; i++) l_run[i] = l_run[i] * c[i] + rs[i];

        // P = exp * group_prob, store into reused K buffer; rescale O
        {
            const float* Gb = Gp + (size_t)b * SS * SS + (size_t)(q0 + 4 * ty) * SS + k0 + 4 * tx;
#pragma unroll
            for (int i = 0; i < 4; i++) {
                float4 gv = *(const float4*)(Gb + (size_t)i * SS);
                float4 ps;
                ps.x = Sv[i][0] * gv.x; ps.y = Sv[i][1] * gv.y;
                ps.z = Sv[i][2] * gv.z; ps.w = Sv[i][3] * gv.w;
                *(float4*)&KtPs[(4 * ty + i) * 64 + 4 * tx] = ps;
                Oacc[i][0] *= c[i]; Oacc[i][1] *= c[i];
                Oacc[i][2] *= c[i]; Oacc[i][3] *= c[i];
            }
        }
        __syncthreads();  // P visible

        // O += P * V
#pragma unroll 4
        for (int kk = 0; kk < 64; kk += 4) {
            float pa[4][4];
#pragma unroll
            for (int i = 0; i < 4; i++) {
                float4 v = *(const float4*)&KtPs[(4 * ty + i) * 64 + kk];
                pa[i][0] = v.x; pa[i][1] = v.y; pa[i][2] = v.z; pa[i][3] = v.w;
            }
#pragma unroll
            for (int kq = 0; kq < 4; kq++) {
                float4 vv = *(const float4*)&Vs[(kk + kq) * 64 + 4 * tx];
#pragma unroll
                for (int i = 0; i < 4; i++) {
                    Oacc[i][0] += pa[i][kq] * vv.x;
                    Oacc[i][1] += pa[i][kq] * vv.y;
                    Oacc[i][2] += pa[i][kq] * vv.z;
                    Oacc[i][3] += pa[i][kq] * vv.w;
                }
            }
        }
    }

    // epilogue: normalize by denominator, write [B,S,D] layout (head slice)
#pragma unroll
    for (int i = 0; i < 4; i++) {
        float inv = 1.0f / l_run[i];
        float4 o;
        o.x = Oacc[i][0] * inv; o.y = Oacc[i][1] * inv;
        o.z = Oacc[i][2] * inv; o.w = Oacc[i][3] * inv;
        *(float4*)&Op[(size_t)(b * SS + q0 + 4 * ty + i) * DD + h * DK + 4 * tx] = o;
    }
}

// ---------------------------------------------------------------------------
extern "C" void kernel_launch(void* const* d_in, const int* in_sizes, int n_in,
                              void* d_out, int out_size)
{
    const float* query = (const float*)d_in[0];
    const float* key   = (const float*)d_in[1];
    const float* value = (const float*)d_in[2];
    const float* gprob = (const float*)d_in[3];
    const int*   mask  = (const int*)d_in[4];
    const float* Wq = (const float*)d_in[5];
    const float* bq = (const float*)d_in[6];
    const float* Wk = (const float*)d_in[7];
    const float* bk = (const float*)d_in[8];
    const float* Wv = (const float*)d_in[9];
    const float* bv = (const float*)d_in[10];
    const float* Wo = (const float*)d_in[11];
    const float* bo = (const float*)d_in[12];
    float* out = (float*)d_out;

    float *gq, *gk, *gv, *gx;
    cudaGetSymbolAddress((void**)&gq, g_q);
    cudaGetSymbolAddress((void**)&gk, g_k);
    cudaGetSymbolAddress((void**)&gv, g_v);
    cudaGetSymbolAddress((void**)&gx, g_x);

    dim3 gb(DD / 128, MROWS / 128);  // (8, 32)
    gemm_nt<<<gb, 256>>>(query, Wq, bq, gq, MROWS, DD, DD);
    gemm_nt<<<gb, 256>>>(key,   Wk, bk, gk, MROWS, DD, DD);
    gemm_nt<<<gb, 256>>>(value, Wv, bv, gv, MROWS, DD, DD);

    attn_kernel<<<dim3(SS / 64, HH, BB), 256>>>(gq, gk, gv, gprob, mask, gx);

    gemm_nt<<<gb, 256>>>(gx, Wo, bo, out, MROWS, DD, DD);
}

// round 3
// speedup vs baseline: 1.2938x; 1.2938x over previous
#include <cuda_runtime.h>
#include <cstdint>
#include <math.h>

// Problem constants
#define BB 2
#define SS 2048
#define DD 1024
#define HH 16
#define DK 64
#define MROWS (BB * SS)   // 4096

// Scratch (alloc-free rule: __device__ globals)
__device__ float g_q[BB * SS * DD];
__device__ float g_k[BB * SS * DD];
__device__ float g_v[BB * SS * DD];
__device__ float g_x[BB * SS * DD];
__device__ float g_ra[MROWS * DD];   // tf32-rounded activation
__device__ float g_rw[DD * DD];      // tf32-rounded weight

// ---------------------------------------------------------------------------
// Helpers
// ---------------------------------------------------------------------------
__device__ __forceinline__ uint32_t smem_to_u32(const void* p) {
    uint32_t a;
    asm("{ .reg .u64 t; cvta.to.shared.u64 t, %1; cvt.u32.u64 %0, t; }" : "=r"(a) : "l"(p));
    return a;
}
#define CP_ASYNC16(dst, src) \
    asm volatile("cp.async.cg.shared.global [%0], [%1], 16;" :: "r"((uint32_t)(dst)), "l"(src))
#define CP_COMMIT() asm volatile("cp.async.commit_group;" ::: "memory")
#define CP_WAIT2()  asm volatile("cp.async.wait_group 2;" ::: "memory")

// m16n8k8 tf32 MMA (row.col): D = A * B + D
__device__ __forceinline__ void mma_tf32(float* c, const uint32_t* a, const uint32_t* b) {
    asm volatile(
        "mma.sync.aligned.m16n8k8.row.col.f32.tf32.tf32.f32 "
        "{%0,%1,%2,%3}, {%4,%5,%6,%7}, {%8,%9}, {%0,%1,%2,%3};"
        : "+f"(c[0]), "+f"(c[1]), "+f"(c[2]), "+f"(c[3])
        : "r"(a[0]), "r"(a[1]), "r"(a[2]), "r"(a[3]), "r"(b[0]), "r"(b[1]));
}

// ---------------------------------------------------------------------------
// Elementwise RNA round to tf32 (keeps fp32 storage)
// ---------------------------------------------------------------------------
__global__ __launch_bounds__(256) void round_tf32(const float* __restrict__ in,
                                                  float* __restrict__ out) {
    int i = (blockIdx.x * 256 + threadIdx.x) * 4;
    float4 v = *(const float4*)(in + i);
    uint32_t a, b, c, d;
    asm("cvt.rna.tf32.f32 %0, %1;" : "=r"(a) : "f"(v.x));
    asm("cvt.rna.tf32.f32 %0, %1;" : "=r"(b) : "f"(v.y));
    asm("cvt.rna.tf32.f32 %0, %1;" : "=r"(c) : "f"(v.z));
    asm("cvt.rna.tf32.f32 %0, %1;" : "=r"(d) : "f"(v.w));
    float4 o;
    o.x = __uint_as_float(a); o.y = __uint_as_float(b);
    o.z = __uint_as_float(c); o.w = __uint_as_float(d);
    *(float4*)(out + i) = o;
}

// ---------------------------------------------------------------------------
// mma.sync tf32 GEMM: C[M,N] = A[M,K] * W[N,K]^T + bias  (M=4096, N=K=1024)
// 128x128x32 tiles, 256 threads (8 warps, 2x4), warp tile 64x32.
// Smem: per stage A[128][36] + W[128][36] floats (pad 36 => conflict-free
// fragment loads: bank = (4g + tig + 8ks) % 32, all-distinct).
// 4-stage cp.async pipeline.
// ---------------------------------------------------------------------------
#define G_NS 4
#define G_PAD 36
#define G_TILE_B (128 * G_PAD * 4)        // 18432
#define G_STAGE_B (2 * G_TILE_B)          // 36864
#define G_SMEM_TOTAL (G_NS * G_STAGE_B)   // 147456

__global__ __launch_bounds__(256, 1) void gemm_tc(
    const float* __restrict__ A, const float* __restrict__ W,
    const float* __restrict__ bias, float* __restrict__ C)
{
    extern __shared__ __align__(128) char smem[];
    const uint32_t sb = smem_to_u32(smem);
    const int t = threadIdx.x;
    const int wid = t >> 5, lane = t & 31;
    const int g = lane >> 2, tig = lane & 3;      // groupID, thread-in-group
    const int wm = wid >> 2, wn = wid & 3;        // warp grid 2x4
    const int m0 = blockIdx.y * 128, n0 = blockIdx.x * 128;
    const int K = DD;

    const float* Ab = A + (size_t)m0 * K;
    const float* Wb = W + (size_t)n0 * K;

    // per-thread global->smem mapping: row = t>>1, chunks (t&1)*4 .. +3
    const int lrow = t >> 1;
    const int cc = (t & 1) * 4;

    auto load_stage = [&](int s, int kt) {
        uint32_t sa = sb + s * G_STAGE_B + lrow * (G_PAD * 4) + cc * 16;
        uint32_t sw = sa + G_TILE_B;
        const float* ga = Ab + (size_t)lrow * K + kt * 32 + cc * 4;
        const float* gw = Wb + (size_t)lrow * K + kt * 32 + cc * 4;
#pragma unroll
        for (int i = 0; i < 4; i++) {
            CP_ASYNC16(sa + i * 16, ga + i * 4);
            CP_ASYNC16(sw + i * 16, gw + i * 4);
        }
    };

    float acc[4][4][4];
#pragma unroll
    for (int i = 0; i < 4; i++)
#pragma unroll
        for (int j = 0; j < 4; j++)
#pragma unroll
            for (int k = 0; k < 4; k++) acc[i][j][k] = 0.0f;

    const int NT = K / 32;  // 32
    for (int s = 0; s < G_NS - 1; s++) { load_stage(s, s); CP_COMMIT(); }

    for (int kt = 0; kt < NT; kt++) {
        CP_WAIT2();
        __syncthreads();
        {
            const float* As = (const float*)(smem + (kt & 3) * G_STAGE_B);
            const float* Ws = (const float*)(smem + (kt & 3) * G_STAGE_B + G_TILE_B);
#pragma unroll
            for (int ks = 0; ks < 4; ks++) {
                const int kc = ks * 8 + tig;
                uint32_t a[4][4], b[4][2];
#pragma unroll
                for (int mf = 0; mf < 4; mf++) {
                    const int r = wm * 64 + mf * 16 + g;
                    a[mf][0] = __float_as_uint(As[r * G_PAD + kc]);
                    a[mf][1] = __float_as_uint(As[(r + 8) * G_PAD + kc]);
                    a[mf][2] = __float_as_uint(As[r * G_PAD + kc + 4]);
                    a[mf][3] = __float_as_uint(As[(r + 8) * G_PAD + kc + 4]);
                }
#pragma unroll
                for (int nf = 0; nf < 4; nf++) {
                    const int r = wn * 32 + nf * 8 + g;
                    b[nf][0] = __float_as_uint(Ws[r * G_PAD + kc]);
                    b[nf][1] = __float_as_uint(Ws[r * G_PAD + kc + 4]);
                }
#pragma unroll
                for (int mf = 0; mf < 4; mf++)
#pragma unroll
                    for (int nf = 0; nf < 4; nf++)
                        mma_tf32(acc[mf][nf], a[mf], b[nf]);
            }
        }
        __syncthreads();
        const int nx = kt + G_NS - 1;
        if (nx < NT) { load_stage(nx & 3, nx); CP_COMMIT(); }
    }

    // epilogue: add bias, store. c0/c1 -> (row, 2*tig), c2/c3 -> (row+8, 2*tig)
#pragma unroll
    for (int mf = 0; mf < 4; mf++) {
        const int r = m0 + wm * 64 + mf * 16 + g;
#pragma unroll
        for (int nf = 0; nf < 4; nf++) {
            const int c = n0 + wn * 32 + nf * 8 + tig * 2;
            const float b0 = bias[c], b1 = bias[c + 1];
            float2 v0 = make_float2(acc[mf][nf][0] + b0, acc[mf][nf][1] + b1);
            float2 v1 = make_float2(acc[mf][nf][2] + b0, acc[mf][nf][3] + b1);
            *(float2*)&C[(size_t)r * DD + c] = v0;
            *(float2*)&C[(size_t)(r + 8) * DD + c] = v1;
        }
    }
}

// ---------------------------------------------------------------------------
// Flash attention (unchanged): one block per (b, h, 64-row q tile).
// ---------------------------------------------------------------------------
__global__ __launch_bounds__(256) void attn_kernel(
    const float* __restrict__ Qp, const float* __restrict__ Kp,
    const float* __restrict__ Vp, const float* __restrict__ Gp,
    const int* __restrict__ Mp, float* __restrict__ Op)
{
    __shared__ float Qt[64 * 64];
    __shared__ float KtPs[64 * 64];
    __shared__ float Vs[64 * 64];

    const int b = blockIdx.z, h = blockIdx.y;
    const int q0 = blockIdx.x * 64;
    const int t = threadIdx.x;
    const int tx = t & 15, ty = t >> 4;
    const int lr = t >> 2, ld0 = (t & 3) * 16;

    {
        const float* Qb = Qp + (size_t)(b * SS + q0 + lr) * DD + h * DK + ld0;
#pragma unroll
        for (int i = 0; i < 4; i++) {
            float4 v = *(const float4*)(Qb + 4 * i);
            Qt[(ld0 + 4 * i + 0) * 64 + lr] = v.x;
            Qt[(ld0 + 4 * i + 1) * 64 + lr] = v.y;
            Qt[(ld0 + 4 * i + 2) * 64 + lr] = v.z;
            Qt[(ld0 + 4 * i + 3) * 64 + lr] = v.w;
        }
    }

    float m_run[4], l_run[4], Oacc[4][4];
#pragma unroll
    for (int i = 0; i < 4; i++) {
        m_run[i] = -1e30f;
        l_run[i] = 0.0f;
#pragma unroll
        for (int j = 0; j < 4; j++) Oacc[i][j] = 0.0f;
    }

    for (int k0 = 0; k0 < SS; k0 += 64) {
        __syncthreads();
        {
            const float* Kb = Kp + (size_t)(b * SS + k0 + lr) * DD + h * DK + ld0;
            const float* Vb = Vp + (size_t)(b * SS + k0 + lr) * DD + h * DK + ld0;
#pragma unroll
            for (int i = 0; i < 4; i++) {
                float4 kv = *(const float4*)(Kb + 4 * i);
                KtPs[(ld0 + 4 * i + 0) * 64 + lr] = kv.x;
                KtPs[(ld0 + 4 * i + 1) * 64 + lr] = kv.y;
                KtPs[(ld0 + 4 * i + 2) * 64 + lr] = kv.z;
                KtPs[(ld0 + 4 * i + 3) * 64 + lr] = kv.w;
                float4 vv = *(const float4*)(Vb + 4 * i);
                *(float4*)&Vs[lr * 64 + ld0 + 4 * i] = vv;
            }
        }
        int mk[4];
#pragma unroll
        for (int j = 0; j < 4; j++) mk[j] = Mp[b * SS + k0 + 4 * tx + j];
        __syncthreads();

        float Sv[4][4];
#pragma unroll
        for (int i = 0; i < 4; i++)
#pragma unroll
            for (int j = 0; j < 4; j++) Sv[i][j] = 0.0f;
#pragma unroll 8
        for (int d = 0; d < 64; d++) {
            float4 qa = *(const float4*)&Qt[d * 64 + 4 * ty];
            float4 kb = *(const float4*)&KtPs[d * 64 + 4 * tx];
            float a[4] = {qa.x, qa.y, qa.z, qa.w};
            float bl[4] = {kb.x, kb.y, kb.z, kb.w};
#pragma unroll
            for (int i = 0; i < 4; i++)
#pragma unroll
                for (int j = 0; j < 4; j++) Sv[i][j] += a[i] * bl[j];
        }
        __syncthreads();

        const float scale = 0.125f;
        float mt[4];
#pragma unroll
        for (int i = 0; i < 4; i++) {
            const int rowq = q0 + 4 * ty + i;
#pragma unroll
            for (int j = 0; j < 4; j++) {
                float s = Sv[i][j] * scale;
                const int colk = k0 + 4 * tx + j;
                if (mk[j] == 0 && colk != rowq) s = -1e9f;
                Sv[i][j] = s;
            }
            mt[i] = fmaxf(fmaxf(Sv[i][0], Sv[i][1]), fmaxf(Sv[i][2], Sv[i][3]));
        }
#pragma unroll
        for (int off = 1; off < 16; off <<= 1)
#pragma unroll
            for (int i = 0; i < 4; i++)
                mt[i] = fmaxf(mt[i], __shfl_xor_sync(0xffffffffu, mt[i], off));

        float c[4], rs[4];
#pragma unroll
        for (int i = 0; i < 4; i++) {
            float m_new = fmaxf(m_run[i], mt[i]);
            c[i] = __expf(m_run[i] - m_new);
            m_run[i] = m_new;
            rs[i] = 0.0f;
#pragma unroll
            for (int j = 0; j < 4; j++) {
                float p = __expf(Sv[i][j] - m_new);
                Sv[i][j] = p;
                rs[i] += p;
            }
        }
#pragma unroll
        for (int off = 1; off < 16; off <<= 1)
#pragma unroll
            for (int i = 0; i < 4; i++)
                rs[i] += __shfl_xor_sync(0xffffffffu, rs[i], off);
#pragma unroll
        for (int i = 0; i < 4; i++) l_run[i] = l_run[i] * c[i] + rs[i];

        {
            const float* Gb = Gp + (size_t)b * SS * SS + (size_t)(q0 + 4 * ty) * SS + k0 + 4 * tx;
#pragma unroll
            for (int i = 0; i < 4; i++) {
                float4 gv = *(const float4*)(Gb + (size_t)i * SS);
                float4 ps;
                ps.x = Sv[i][0] * gv.x; ps.y = Sv[i][1] * gv.y;
                ps.z = Sv[i][2] * gv.z; ps.w = Sv[i][3] * gv.w;
                *(float4*)&KtPs[(4 * ty + i) * 64 + 4 * tx] = ps;
                Oacc[i][0] *= c[i]; Oacc[i][1] *= c[i];
                Oacc[i][2] *= c[i]; Oacc[i][3] *= c[i];
            }
        }
        __syncthreads();

#pragma unroll 4
        for (int kk = 0; kk < 64; kk += 4) {
            float pa[4][4];
#pragma unroll
            for (int i = 0; i < 4; i++) {
                float4 v = *(const float4*)&KtPs[(4 * ty + i) * 64 + kk];
                pa[i][0] = v.x; pa[i][1] = v.y; pa[i][2] = v.z; pa[i][3] = v.w;
            }
#pragma unroll
            for (int kq = 0; kq < 4; kq++) {
                float4 vv = *(const float4*)&Vs[(kk + kq) * 64 + 4 * tx];
#pragma unroll
                for (int i = 0; i < 4; i++) {
                    Oacc[i][0] += pa[i][kq] * vv.x;
                    Oacc[i][1] += pa[i][kq] * vv.y;
                    Oacc[i][2] += pa[i][kq] * vv.z;
                    Oacc[i][3] += pa[i][kq] * vv.w;
                }
            }
        }
    }

#pragma unroll
    for (int i = 0; i < 4; i++) {
        float inv = 1.0f / l_run[i];
        float4 o;
        o.x = Oacc[i][0] * inv; o.y = Oacc[i][1] * inv;
        o.z = Oacc[i][2] * inv; o.w = Oacc[i][3] * inv;
        *(float4*)&Op[(size_t)(b * SS + q0 + 4 * ty + i) * DD + h * DK + 4 * tx] = o;
    }
}

// ---------------------------------------------------------------------------
extern "C" void kernel_launch(void* const* d_in, const int* in_sizes, int n_in,
                              void* d_out, int out_size)
{
    const float* query = (const float*)d_in[0];
    const float* key   = (const float*)d_in[1];
    const float* value = (const float*)d_in[2];
    const float* gprob = (const float*)d_in[3];
    const int*   mask  = (const int*)d_in[4];
    const float* Wq = (const float*)d_in[5];
    const float* bq = (const float*)d_in[6];
    const float* Wk = (const float*)d_in[7];
    const float* bk = (const float*)d_in[8];
    const float* Wv = (const float*)d_in[9];
    const float* bv = (const float*)d_in[10];
    const float* Wo = (const float*)d_in[11];
    const float* bo = (const float*)d_in[12];
    float* out = (float*)d_out;

    float *gq, *gk, *gv, *gx, *ra, *rw;
    cudaGetSymbolAddress((void**)&gq, g_q);
    cudaGetSymbolAddress((void**)&gk, g_k);
    cudaGetSymbolAddress((void**)&gv, g_v);
    cudaGetSymbolAddress((void**)&gx, g_x);
    cudaGetSymbolAddress((void**)&ra, g_ra);
    cudaGetSymbolAddress((void**)&rw, g_rw);

    cudaFuncSetAttribute(gemm_tc, cudaFuncAttributeMaxDynamicSharedMemorySize, G_SMEM_TOTAL);

    const int AB = MROWS * DD / 4 / 256;  // 4096 blocks
    const int WB = DD * DD / 4 / 256;     // 1024 blocks
    dim3 gg(DD / 128, MROWS / 128);       // (8, 32)

    round_tf32<<<AB, 256>>>(query, ra);
    round_tf32<<<WB, 256>>>(Wq, rw);
    gemm_tc<<<gg, 256, G_SMEM_TOTAL>>>(ra, rw, bq, gq);

    round_tf32<<<AB, 256>>>(key, ra);
    round_tf32<<<WB, 256>>>(Wk, rw);
    gemm_tc<<<gg, 256, G_SMEM_TOTAL>>>(ra, rw, bk, gk);

    round_tf32<<<AB, 256>>>(value, ra);
    round_tf32<<<WB, 256>>>(Wv, rw);
    gemm_tc<<<gg, 256, G_SMEM_TOTAL>>>(ra, rw, bv, gv);

    attn_kernel<<<dim3(SS / 64, HH, BB), 256>>>(gq, gk, gv, gprob, mask, gx);

    round_tf32<<<AB, 256>>>(gx, ra);
    round_tf32<<<WB, 256>>>(Wo, rw);
    gemm_tc<<<gg, 256, G_SMEM_TOTAL>>>(ra, rw, bo, out);
}

// round 4
// speedup vs baseline: 2.0083x; 1.5523x over previous
#include <cuda_runtime.h>
#include <cstdint>
#include <math.h>

// Problem constants
#define BB 2
#define SS 2048
#define DD 1024
#define HH 16
#define DK 64
#define MROWS (BB * SS)   // 4096

// Scratch (alloc-free rule: __device__ globals)
__device__ float g_q[BB * SS * DD];
__device__ float g_k[BB * SS * DD];
__device__ float g_v[BB * SS * DD];
__device__ float g_x[BB * SS * DD];
__device__ float g_ra[MROWS * DD];   // tf32-rounded activation
__device__ float g_rw[DD * DD];      // tf32-rounded weight

// ---------------------------------------------------------------------------
// Helpers
// ---------------------------------------------------------------------------
__device__ __forceinline__ uint32_t smem_to_u32(const void* p) {
    uint32_t a;
    asm("{ .reg .u64 t; cvta.to.shared.u64 t, %1; cvt.u32.u64 %0, t; }" : "=r"(a) : "l"(p));
    return a;
}
__device__ __forceinline__ float tf32r(float x) {
    uint32_t u;
    asm("cvt.rna.tf32.f32 %0, %1;" : "=r"(u) : "f"(x));
    return __uint_as_float(u);
}
#define CP_ASYNC16(dst, src) \
    asm volatile("cp.async.cg.shared.global [%0], [%1], 16;" :: "r"((uint32_t)(dst)), "l"(src))
#define CP_COMMIT() asm volatile("cp.async.commit_group;" ::: "memory")
#define CP_WAIT2()  asm volatile("cp.async.wait_group 2;" ::: "memory")

// m16n8k8 tf32 MMA (row.col): D = A * B + D
__device__ __forceinline__ void mma_tf32(float* c, const uint32_t* a, const uint32_t* b) {
    asm volatile(
        "mma.sync.aligned.m16n8k8.row.col.f32.tf32.tf32.f32 "
        "{%0,%1,%2,%3}, {%4,%5,%6,%7}, {%8,%9}, {%0,%1,%2,%3};"
        : "+f"(c[0]), "+f"(c[1]), "+f"(c[2]), "+f"(c[3])
        : "r"(a[0]), "r"(a[1]), "r"(a[2]), "r"(a[3]), "r"(b[0]), "r"(b[1]));
}

// ---------------------------------------------------------------------------
// Elementwise RNA round to tf32 (keeps fp32 storage)
// ---------------------------------------------------------------------------
__global__ __launch_bounds__(256) void round_tf32(const float* __restrict__ in,
                                                  float* __restrict__ out) {
    int i = (blockIdx.x * 256 + threadIdx.x) * 4;
    float4 v = *(const float4*)(in + i);
    float4 o;
    o.x = tf32r(v.x); o.y = tf32r(v.y); o.z = tf32r(v.z); o.w = tf32r(v.w);
    *(float4*)(out + i) = o;
}

// ---------------------------------------------------------------------------
// mma.sync tf32 GEMM: C[M,N] = A[M,K] * W[N,K]^T + bias  (unchanged from R2)
// ---------------------------------------------------------------------------
#define G_NS 4
#define G_PAD 36
#define G_TILE_B (128 * G_PAD * 4)        // 18432
#define G_STAGE_B (2 * G_TILE_B)          // 36864
#define G_SMEM_TOTAL (G_NS * G_STAGE_B)   // 147456

__global__ __launch_bounds__(256, 1) void gemm_tc(
    const float* __restrict__ A, const float* __restrict__ W,
    const float* __restrict__ bias, float* __restrict__ C)
{
    extern __shared__ __align__(128) char smem[];
    const uint32_t sb = smem_to_u32(smem);
    const int t = threadIdx.x;
    const int wid = t >> 5, lane = t & 31;
    const int g = lane >> 2, tig = lane & 3;
    const int wm = wid >> 2, wn = wid & 3;
    const int m0 = blockIdx.y * 128, n0 = blockIdx.x * 128;
    const int K = DD;

    const float* Ab = A + (size_t)m0 * K;
    const float* Wb = W + (size_t)n0 * K;

    const int lrow = t >> 1;
    const int cc = (t & 1) * 4;

    auto load_stage = [&](int s, int kt) {
        uint32_t sa = sb + s * G_STAGE_B + lrow * (G_PAD * 4) + cc * 16;
        uint32_t sw = sa + G_TILE_B;
        const float* ga = Ab + (size_t)lrow * K + kt * 32 + cc * 4;
        const float* gw = Wb + (size_t)lrow * K + kt * 32 + cc * 4;
#pragma unroll
        for (int i = 0; i < 4; i++) {
            CP_ASYNC16(sa + i * 16, ga + i * 4);
            CP_ASYNC16(sw + i * 16, gw + i * 4);
        }
    };

    float acc[4][4][4];
#pragma unroll
    for (int i = 0; i < 4; i++)
#pragma unroll
        for (int j = 0; j < 4; j++)
#pragma unroll
            for (int k = 0; k < 4; k++) acc[i][j][k] = 0.0f;

    const int NT = K / 32;
    for (int s = 0; s < G_NS - 1; s++) { load_stage(s, s); CP_COMMIT(); }

    for (int kt = 0; kt < NT; kt++) {
        CP_WAIT2();
        __syncthreads();
        {
            const float* As = (const float*)(smem + (kt & 3) * G_STAGE_B);
            const float* Ws = (const float*)(smem + (kt & 3) * G_STAGE_B + G_TILE_B);
#pragma unroll
            for (int ks = 0; ks < 4; ks++) {
                const int kc = ks * 8 + tig;
                uint32_t a[4][4], b[4][2];
#pragma unroll
                for (int mf = 0; mf < 4; mf++) {
                    const int r = wm * 64 + mf * 16 + g;
                    a[mf][0] = __float_as_uint(As[r * G_PAD + kc]);
                    a[mf][1] = __float_as_uint(As[(r + 8) * G_PAD + kc]);
                    a[mf][2] = __float_as_uint(As[r * G_PAD + kc + 4]);
                    a[mf][3] = __float_as_uint(As[(r + 8) * G_PAD + kc + 4]);
                }
#pragma unroll
                for (int nf = 0; nf < 4; nf++) {
                    const int r = wn * 32 + nf * 8 + g;
                    b[nf][0] = __float_as_uint(Ws[r * G_PAD + kc]);
                    b[nf][1] = __float_as_uint(Ws[r * G_PAD + kc + 4]);
                }
#pragma unroll
                for (int mf = 0; mf < 4; mf++)
#pragma unroll
                    for (int nf = 0; nf < 4; nf++)
                        mma_tf32(acc[mf][nf], a[mf], b[nf]);
            }
        }
        __syncthreads();
        const int nx = kt + G_NS - 1;
        if (nx < NT) { load_stage(nx & 3, nx); CP_COMMIT(); }
    }

#pragma unroll
    for (int mf = 0; mf < 4; mf++) {
        const int r = m0 + wm * 64 + mf * 16 + g;
#pragma unroll
        for (int nf = 0; nf < 4; nf++) {
            const int c = n0 + wn * 32 + nf * 8 + tig * 2;
            const float b0 = bias[c], b1 = bias[c + 1];
            float2 v0 = make_float2(acc[mf][nf][0] + b0, acc[mf][nf][1] + b1);
            float2 v1 = make_float2(acc[mf][nf][2] + b0, acc[mf][nf][3] + b1);
            *(float2*)&C[(size_t)r * DD + c] = v0;
            *(float2*)&C[(size_t)(r + 8) * DD + c] = v1;
        }
    }
}

// ---------------------------------------------------------------------------
// mma.sync tf32 flash attention.
// Block: 128 q-rows x one (b,h). 256 threads / 8 warps; warp w owns q-rows
// [16w, 16w+16). Per 64-key tile: S = Q K^T (mma), warp-local online softmax
// on C fragments, P = exp * group_prob -> tf32 -> smem, O += P V (mma).
// Smem row stride 68 floats (== 4 mod 32) => conflict-free fragment LDS.
// ---------------------------------------------------------------------------
#define AT_PAD 68
#define AT_QS 0
#define AT_KS (128 * AT_PAD)
#define AT_VT (AT_KS + 64 * AT_PAD)
#define AT_PS (AT_VT + 64 * AT_PAD)
#define AT_MS (AT_PS + 128 * AT_PAD)
#define AT_SMEM_FLOATS (AT_MS + 64)
#define AT_SMEM_BYTES (AT_SMEM_FLOATS * 4)

__global__ __launch_bounds__(256, 1) void attn_tc(
    const float* __restrict__ Qp, const float* __restrict__ Kp,
    const float* __restrict__ Vp, const float* __restrict__ Gp,
    const int* __restrict__ Mp, float* __restrict__ Op)
{
    extern __shared__ __align__(16) float sm[];
    float* Qs = sm + AT_QS;
    float* Ks = sm + AT_KS;
    float* Vt = sm + AT_VT;
    float* Ps = sm + AT_PS;
    int* Ms = (int*)(sm + AT_MS);

    const int b = blockIdx.z, h = blockIdx.y;
    const int q0 = blockIdx.x * 128;
    const int t = threadIdx.x;
    const int wid = t >> 5, lane = t & 31;
    const int g = lane >> 2, tig = lane & 3;

    // ---- load Q tile (rounded to tf32), natural layout [qrow][dk] ----
    {
        const int r = t >> 1, c0 = (t & 1) * 32;
        const float* src = Qp + (size_t)(b * SS + q0 + r) * DD + h * DK + c0;
#pragma unroll
        for (int i = 0; i < 8; i++) {
            float4 v = *(const float4*)(src + 4 * i);
            float4 o;
            o.x = tf32r(v.x); o.y = tf32r(v.y); o.z = tf32r(v.z); o.w = tf32r(v.w);
            *(float4*)&Qs[r * AT_PAD + c0 + 4 * i] = o;
        }
    }

    float m0r = -1e30f, m1r = -1e30f;   // running max, rows g / g+8
    float l0r = 0.0f, l1r = 0.0f;       // running denom
    float O[8][4];
#pragma unroll
    for (int d = 0; d < 8; d++)
#pragma unroll
        for (int j = 0; j < 4; j++) O[d][j] = 0.0f;

    const int rq0 = q0 + 16 * wid + g;
    const int rq1 = rq0 + 8;

    for (int k0 = 0; k0 < SS; k0 += 64) {
        __syncthreads();  // prior iteration done with Ks/Vt
        // ---- load K (natural) and V (transposed, d-major), rounded ----
        {
            const int r = t >> 2, c0 = (t & 3) * 16;
            const float* ksrc = Kp + (size_t)(b * SS + k0 + r) * DD + h * DK + c0;
            const float* vsrc = Vp + (size_t)(b * SS + k0 + r) * DD + h * DK + c0;
#pragma unroll
            for (int i = 0; i < 4; i++) {
                float4 kv = *(const float4*)(ksrc + 4 * i);
                float4 ko;
                ko.x = tf32r(kv.x); ko.y = tf32r(kv.y);
                ko.z = tf32r(kv.z); ko.w = tf32r(kv.w);
                *(float4*)&Ks[r * AT_PAD + c0 + 4 * i] = ko;
                float4 vv = *(const float4*)(vsrc + 4 * i);
                const int c = c0 + 4 * i;
                Vt[(c + 0) * AT_PAD + r] = tf32r(vv.x);
                Vt[(c + 1) * AT_PAD + r] = tf32r(vv.y);
                Vt[(c + 2) * AT_PAD + r] = tf32r(vv.z);
                Vt[(c + 3) * AT_PAD + r] = tf32r(vv.w);
            }
        }
        if (t < 64) Ms[t] = Mp[b * SS + k0 + t];
        __syncthreads();

        // ---- S = Q K^T : 8 k-steps x 8 n-frags ----
        float S[8][4];
#pragma unroll
        for (int nf = 0; nf < 8; nf++)
#pragma unroll
            for (int j = 0; j < 4; j++) S[nf][j] = 0.0f;
#pragma unroll
        for (int ks = 0; ks < 8; ks++) {
            const int kc = 8 * ks + tig;
            uint32_t a[4];
            a[0] = __float_as_uint(Qs[(16 * wid + g) * AT_PAD + kc]);
            a[1] = __float_as_uint(Qs[(16 * wid + g + 8) * AT_PAD + kc]);
            a[2] = __float_as_uint(Qs[(16 * wid + g) * AT_PAD + kc + 4]);
            a[3] = __float_as_uint(Qs[(16 * wid + g + 8) * AT_PAD + kc + 4]);
#pragma unroll
            for (int nf = 0; nf < 8; nf++) {
                uint32_t bfr[2];
                bfr[0] = __float_as_uint(Ks[(8 * nf + g) * AT_PAD + kc]);
                bfr[1] = __float_as_uint(Ks[(8 * nf + g) * AT_PAD + kc + 4]);
                mma_tf32(S[nf], a, bfr);
            }
        }

        // ---- scale + mask + warp-local online softmax ----
        const float scale = 0.125f;
        float mx0 = -1e30f, mx1 = -1e30f;
#pragma unroll
        for (int nf = 0; nf < 8; nf++) {
            const int cb = k0 + 8 * nf + 2 * tig;
            const int mk0 = Ms[8 * nf + 2 * tig];
            const int mk1 = Ms[8 * nf + 2 * tig + 1];
            float s0 = S[nf][0] * scale;
            float s1 = S[nf][1] * scale;
            float s2 = S[nf][2] * scale;
            float s3 = S[nf][3] * scale;
            if (mk0 == 0 && cb != rq0) s0 = -1e9f;
            if (mk1 == 0 && cb + 1 != rq0) s1 = -1e9f;
            if (mk0 == 0 && cb != rq1) s2 = -1e9f;
            if (mk1 == 0 && cb + 1 != rq1) s3 = -1e9f;
            S[nf][0] = s0; S[nf][1] = s1; S[nf][2] = s2; S[nf][3] = s3;
            mx0 = fmaxf(mx0, fmaxf(s0, s1));
            mx1 = fmaxf(mx1, fmaxf(s2, s3));
        }
        mx0 = fmaxf(mx0, __shfl_xor_sync(0xffffffffu, mx0, 1));
        mx0 = fmaxf(mx0, __shfl_xor_sync(0xffffffffu, mx0, 2));
        mx1 = fmaxf(mx1, __shfl_xor_sync(0xffffffffu, mx1, 1));
        mx1 = fmaxf(mx1, __shfl_xor_sync(0xffffffffu, mx1, 2));

        const float mn0 = fmaxf(m0r, mx0);
        const float mn1 = fmaxf(m1r, mx1);
        const float c0f = __expf(m0r - mn0);
        const float c1f = __expf(m1r - mn1);
        m0r = mn0; m1r = mn1;

        float rs0 = 0.0f, rs1 = 0.0f;
#pragma unroll
        for (int nf = 0; nf < 8; nf++) {
            float p0 = __expf(S[nf][0] - mn0);
            float p1 = __expf(S[nf][1] - mn0);
            float p2 = __expf(S[nf][2] - mn1);
            float p3 = __expf(S[nf][3] - mn1);
            S[nf][0] = p0; S[nf][1] = p1; S[nf][2] = p2; S[nf][3] = p3;
            rs0 += p0 + p1;
            rs1 += p2 + p3;
        }
        rs0 += __shfl_xor_sync(0xffffffffu, rs0, 1);
        rs0 += __shfl_xor_sync(0xffffffffu, rs0, 2);
        rs1 += __shfl_xor_sync(0xffffffffu, rs1, 1);
        rs1 += __shfl_xor_sync(0xffffffffu, rs1, 2);
        l0r = l0r * c0f + rs0;
        l1r = l1r * c1f + rs1;

        // ---- O rescale ----
#pragma unroll
        for (int d = 0; d < 8; d++) {
            O[d][0] *= c0f; O[d][1] *= c0f;
            O[d][2] *= c1f; O[d][3] *= c1f;
        }

        // ---- P = exp * group_prob -> tf32 -> smem ----
        {
            const float* Gb0 = Gp + ((size_t)b * SS + rq0) * SS + k0;
            const float* Gb1 = Gp + ((size_t)b * SS + rq1) * SS + k0;
#pragma unroll
            for (int nf = 0; nf < 8; nf++) {
                const int cc = 8 * nf + 2 * tig;
                float2 g0 = *(const float2*)(Gb0 + cc);
                float2 g1 = *(const float2*)(Gb1 + cc);
                float2 p0, p1;
                p0.x = tf32r(S[nf][0] * g0.x);
                p0.y = tf32r(S[nf][1] * g0.y);
                p1.x = tf32r(S[nf][2] * g1.x);
                p1.y = tf32r(S[nf][3] * g1.y);
                *(float2*)&Ps[(16 * wid + g) * AT_PAD + cc] = p0;
                *(float2*)&Ps[(16 * wid + g + 8) * AT_PAD + cc] = p1;
            }
        }
        __syncwarp();  // Ps rows owned by this warp; make STS visible to LDS

        // ---- O += P V : 8 k-steps x 8 d-frags ----
#pragma unroll
        for (int ks = 0; ks < 8; ks++) {
            const int kc = 8 * ks + tig;
            uint32_t a[4];
            a[0] = __float_as_uint(Ps[(16 * wid + g) * AT_PAD + kc]);
            a[1] = __float_as_uint(Ps[(16 * wid + g + 8) * AT_PAD + kc]);
            a[2] = __float_as_uint(Ps[(16 * wid + g) * AT_PAD + kc + 4]);
            a[3] = __float_as_uint(Ps[(16 * wid + g + 8) * AT_PAD + kc + 4]);
#pragma unroll
            for (int df = 0; df < 8; df++) {
                uint32_t bfr[2];
                bfr[0] = __float_as_uint(Vt[(8 * df + g) * AT_PAD + kc]);
                bfr[1] = __float_as_uint(Vt[(8 * df + g) * AT_PAD + kc + 4]);
                mma_tf32(O[df], a, bfr);
            }
        }
    }

    // ---- epilogue: normalize, store ----
    const float inv0 = 1.0f / l0r;
    const float inv1 = 1.0f / l1r;
    float* o0 = Op + (size_t)(b * SS + rq0) * DD + h * DK;
    float* o1 = Op + (size_t)(b * SS + rq1) * DD + h * DK;
#pragma unroll
    for (int df = 0; df < 8; df++) {
        const int c = 8 * df + 2 * tig;
        float2 v0 = make_float2(O[df][0] * inv0, O[df][1] * inv0);
        float2 v1 = make_float2(O[df][2] * inv1, O[df][3] * inv1);
        *(float2*)(o0 + c) = v0;
        *(float2*)(o1 + c) = v1;
    }
}

// ---------------------------------------------------------------------------
extern "C" void kernel_launch(void* const* d_in, const int* in_sizes, int n_in,
                              void* d_out, int out_size)
{
    const float* query = (const float*)d_in[0];
    const float* key   = (const float*)d_in[1];
    const float* value = (const float*)d_in[2];
    const float* gprob = (const float*)d_in[3];
    const int*   mask  = (const int*)d_in[4];
    const float* Wq = (const float*)d_in[5];
    const float* bq = (const float*)d_in[6];
    const float* Wk = (const float*)d_in[7];
    const float* bk = (const float*)d_in[8];
    const float* Wv = (const float*)d_in[9];
    const float* bv = (const float*)d_in[10];
    const float* Wo = (const float*)d_in[11];
    const float* bo = (const float*)d_in[12];
    float* out = (float*)d_out;

    float *gq, *gk, *gv, *gx, *ra, *rw;
    cudaGetSymbolAddress((void**)&gq, g_q);
    cudaGetSymbolAddress((void**)&gk, g_k);
    cudaGetSymbolAddress((void**)&gv, g_v);
    cudaGetSymbolAddress((void**)&gx, g_x);
    cudaGetSymbolAddress((void**)&ra, g_ra);
    cudaGetSymbolAddress((void**)&rw, g_rw);

    cudaFuncSetAttribute(gemm_tc, cudaFuncAttributeMaxDynamicSharedMemorySize, G_SMEM_TOTAL);
    cudaFuncSetAttribute(attn_tc, cudaFuncAttributeMaxDynamicSharedMemorySize, AT_SMEM_BYTES);

    const int AB = MROWS * DD / 4 / 256;
    const int WB = DD * DD / 4 / 256;
    dim3 gg(DD / 128, MROWS / 128);

    round_tf32<<<AB, 256>>>(query, ra);
    round_tf32<<<WB, 256>>>(Wq, rw);
    gemm_tc<<<gg, 256, G_SMEM_TOTAL>>>(ra, rw, bq, gq);

    round_tf32<<<AB, 256>>>(key, ra);
    round_tf32<<<WB, 256>>>(Wk, rw);
    gemm_tc<<<gg, 256, G_SMEM_TOTAL>>>(ra, rw, bk, gk);

    round_tf32<<<AB, 256>>>(value, ra);
    round_tf32<<<WB, 256>>>(Wv, rw);
    gemm_tc<<<gg, 256, G_SMEM_TOTAL>>>(ra, rw, bv, gv);

    attn_tc<<<dim3(SS / 128, HH, BB), 256, AT_SMEM_BYTES>>>(gq, gk, gv, gprob, mask, gx);

    round_tf32<<<AB, 256>>>(gx, ra);
    round_tf32<<<WB, 256>>>(Wo, rw);
    gemm_tc<<<gg, 256, G_SMEM_TOTAL>>>(ra, rw, bo, out);
}

// round 5
// speedup vs baseline: 3.1210x; 1.5540x over previous
#include <cuda_runtime.h>
#include <cuda_fp16.h>
#include <cstdint>
#include <math.h>

// Problem constants
#define BB 2
#define SS 2048
#define DD 1024
#define HH 16
#define DK 64
#define MROWS (BB * SS)   // 4096

// Scratch (alloc-free rule: __device__ globals)
__device__ float g_q[BB * SS * DD];
__device__ float g_k[BB * SS * DD];
__device__ float g_v[BB * SS * DD];
__device__ float g_x[BB * SS * DD];
__device__ __half g_ha[MROWS * DD];  // half activation
__device__ __half g_hw[DD * DD];     // half weight

// ---------------------------------------------------------------------------
// Helpers
// ---------------------------------------------------------------------------
__device__ __forceinline__ uint32_t smem_to_u32(const void* p) {
    uint32_t a;
    asm("{ .reg .u64 t; cvta.to.shared.u64 t, %1; cvt.u32.u64 %0, t; }" : "=r"(a) : "l"(p));
    return a;
}
__device__ __forceinline__ uint32_t packh2(float x, float y) {
    __half2 h = __floats2half2_rn(x, y);
    return *(uint32_t*)&h;
}
#define CP_ASYNC16(dst, src) \
    asm volatile("cp.async.cg.shared.global [%0], [%1], 16;" :: "r"((uint32_t)(dst)), "l"(src))
#define CP_COMMIT() asm volatile("cp.async.commit_group;" ::: "memory")
#define CP_WAIT2()  asm volatile("cp.async.wait_group 2;" ::: "memory")

// m16n8k16 fp16 MMA (row.col), fp32 accumulate
__device__ __forceinline__ void mma_f16(float* c, const uint32_t* a, const uint32_t* b) {
    asm volatile(
        "mma.sync.aligned.m16n8k16.row.col.f32.f16.f16.f32 "
        "{%0,%1,%2,%3}, {%4,%5,%6,%7}, {%8,%9}, {%0,%1,%2,%3};"
        : "+f"(c[0]), "+f"(c[1]), "+f"(c[2]), "+f"(c[3])
        : "r"(a[0]), "r"(a[1]), "r"(a[2]), "r"(a[3]), "r"(b[0]), "r"(b[1]));
}

// ---------------------------------------------------------------------------
// fp32 -> fp16 convert (8 elems/thread)
// ---------------------------------------------------------------------------
__global__ __launch_bounds__(256) void cvt_half(const float* __restrict__ in,
                                                __half* __restrict__ out) {
    int i = (blockIdx.x * 256 + threadIdx.x) * 8;
    float4 v0 = *(const float4*)(in + i);
    float4 v1 = *(const float4*)(in + i + 4);
    uint4 o;
    o.x = packh2(v0.x, v0.y);
    o.y = packh2(v0.z, v0.w);
    o.z = packh2(v1.x, v1.y);
    o.w = packh2(v1.z, v1.w);
    *(uint4*)(out + i) = o;
}

// ---------------------------------------------------------------------------
// mma.sync fp16 GEMM: C[M,N] = A[M,K] * W[N,K]^T + bias  (M=4096, N=K=1024)
// 128x128x32 tiles, 256 threads (8 warps 2x4), warp tile 64x32.
// Smem: per stage A[128][40h] + W[128][40h] (pad 40 halves = 20 words ->
// fragment LDS banks (20r + tig) % 32 all-distinct). 4-stage cp.async.
// ---------------------------------------------------------------------------
#define G_NS 4
#define G_PADH 40
#define G_ROWB (G_PADH * 2)                // 80 bytes/row
#define G_TILE_B (128 * G_ROWB)            // 10240
#define G_STAGE_B (2 * G_TILE_B)           // 20480
#define G_SMEM_TOTAL (G_NS * G_STAGE_B)    // 81920

__global__ __launch_bounds__(256, 2) void gemm_tc(
    const __half* __restrict__ A, const __half* __restrict__ W,
    const float* __restrict__ bias, float* __restrict__ C)
{
    extern __shared__ __align__(128) char smem[];
    const uint32_t sb = smem_to_u32(smem);
    const int t = threadIdx.x;
    const int wid = t >> 5, lane = t & 31;
    const int g = lane >> 2, tig = lane & 3;
    const int wm = wid >> 2, wn = wid & 3;
    const int m0 = blockIdx.y * 128, n0 = blockIdx.x * 128;
    const int K = DD;

    const __half* Ab = A + (size_t)m0 * K;
    const __half* Wb = W + (size_t)n0 * K;

    const int lrow = t >> 1;           // 0..127
    const int cp = (t & 1) * 2;        // chunk pair: 0 or 2

    auto load_stage = [&](int s, int kt) {
        uint32_t sa = sb + s * G_STAGE_B + lrow * G_ROWB + cp * 16;
        uint32_t sw = sa + G_TILE_B;
        const __half* ga = Ab + (size_t)lrow * K + kt * 32 + cp * 8;
        const __half* gw = Wb + (size_t)lrow * K + kt * 32 + cp * 8;
        CP_ASYNC16(sa, ga);
        CP_ASYNC16(sa + 16, ga + 8);
        CP_ASYNC16(sw, gw);
        CP_ASYNC16(sw + 16, gw + 8);
    };

    float acc[4][4][4];
#pragma unroll
    for (int i = 0; i < 4; i++)
#pragma unroll
        for (int j = 0; j < 4; j++)
#pragma unroll
            for (int k = 0; k < 4; k++) acc[i][j][k] = 0.0f;

    const int NT = K / 32;  // 32
    for (int s = 0; s < G_NS - 1; s++) { load_stage(s, s); CP_COMMIT(); }

    for (int kt = 0; kt < NT; kt++) {
        CP_WAIT2();
        __syncthreads();
        {
            const uint32_t* As = (const uint32_t*)(smem + (kt & 3) * G_STAGE_B);
            const uint32_t* Ws = (const uint32_t*)(smem + (kt & 3) * G_STAGE_B + G_TILE_B);
#pragma unroll
            for (int ks = 0; ks < 2; ks++) {
                const int kw = ks * 8 + tig;  // word offset within 20-word row
                uint32_t a[4][4], b[4][2];
#pragma unroll
                for (int mf = 0; mf < 4; mf++) {
                    const int r = wm * 64 + mf * 16 + g;
                    a[mf][0] = As[r * 20 + kw];
                    a[mf][1] = As[(r + 8) * 20 + kw];
                    a[mf][2] = As[r * 20 + kw + 4];
                    a[mf][3] = As[(r + 8) * 20 + kw + 4];
                }
#pragma unroll
                for (int nf = 0; nf < 4; nf++) {
                    const int r = wn * 32 + nf * 8 + g;
                    b[nf][0] = Ws[r * 20 + kw];
                    b[nf][1] = Ws[r * 20 + kw + 4];
                }
#pragma unroll
                for (int mf = 0; mf < 4; mf++)
#pragma unroll
                    for (int nf = 0; nf < 4; nf++)
                        mma_f16(acc[mf][nf], a[mf], b[nf]);
            }
        }
        __syncthreads();
        const int nx = kt + G_NS - 1;
        if (nx < NT) { load_stage(nx & 3, nx); CP_COMMIT(); }
    }

#pragma unroll
    for (int mf = 0; mf < 4; mf++) {
        const int r = m0 + wm * 64 + mf * 16 + g;
#pragma unroll
        for (int nf = 0; nf < 4; nf++) {
            const int c = n0 + wn * 32 + nf * 8 + tig * 2;
            const float b0 = bias[c], b1 = bias[c + 1];
            float2 v0 = make_float2(acc[mf][nf][0] + b0, acc[mf][nf][1] + b1);
            float2 v1 = make_float2(acc[mf][nf][2] + b0, acc[mf][nf][3] + b1);
            *(float2*)&C[(size_t)r * DD + c] = v0;
            *(float2*)&C[(size_t)(r + 8) * DD + c] = v1;
        }
    }
}

// ---------------------------------------------------------------------------
// mma.sync fp16 flash attention. Structure identical to R3, fp16 engines.
// Block: 128 q-rows x (b,h); 8 warps; warp w owns q-rows [16w,16w+16).
// Row stride 72 halves (36 words == 4 mod 32 -> conflict-free frag LDS).
// ---------------------------------------------------------------------------
#define AT_PADH 72
#define AT_WS 36                       // word stride
#define AT_QS 0
#define AT_KS (128 * AT_PADH)
#define AT_VT (AT_KS + 64 * AT_PADH)
#define AT_PS (AT_VT + 64 * AT_PADH)
#define AT_HALVES (AT_PS + 128 * AT_PADH)
#define AT_SMEM_BYTES (AT_HALVES * 2 + 256)

__global__ __launch_bounds__(256, 1) void attn_tc(
    const float* __restrict__ Qp, const float* __restrict__ Kp,
    const float* __restrict__ Vp, const float* __restrict__ Gp,
    const int* __restrict__ Mp, float* __restrict__ Op)
{
    extern __shared__ __align__(16) __half smh[];
    __half* Qs = smh + AT_QS;
    __half* Ks = smh + AT_KS;
    __half* Vt = smh + AT_VT;
    __half* Ps = smh + AT_PS;
    int* Ms = (int*)(smh + AT_HALVES);

    const int b = blockIdx.z, h = blockIdx.y;
    const int q0 = blockIdx.x * 128;
    const int t = threadIdx.x;
    const int wid = t >> 5, lane = t & 31;
    const int g = lane >> 2, tig = lane & 3;

    // ---- load Q tile -> fp16 smem, natural [qrow][dk] ----
    {
        const int r = t >> 1, c0 = (t & 1) * 32;
        const float* src = Qp + (size_t)(b * SS + q0 + r) * DD + h * DK + c0;
        uint32_t* dst = (uint32_t*)&Qs[r * AT_PADH + c0];
#pragma unroll
        for (int i = 0; i < 8; i++) {
            float4 v = *(const float4*)(src + 4 * i);
            dst[2 * i] = packh2(v.x, v.y);
            dst[2 * i + 1] = packh2(v.z, v.w);
        }
    }

    float m0r = -1e30f, m1r = -1e30f;
    float l0r = 0.0f, l1r = 0.0f;
    float O[8][4];
#pragma unroll
    for (int d = 0; d < 8; d++)
#pragma unroll
        for (int j = 0; j < 4; j++) O[d][j] = 0.0f;

    const int rq0 = q0 + 16 * wid + g;
    const int rq1 = rq0 + 8;
    const uint32_t* Q32 = (const uint32_t*)Qs;
    const uint32_t* K32 = (const uint32_t*)Ks;
    const uint32_t* V32 = (const uint32_t*)Vt;
    const uint32_t* P32 = (const uint32_t*)Ps;

    for (int k0 = 0; k0 < SS; k0 += 64) {
        __syncthreads();
        // ---- load K (natural) and V (transposed d-major) as fp16 ----
        {
            const int r = t >> 2, c0 = (t & 3) * 16;
            const float* ksrc = Kp + (size_t)(b * SS + k0 + r) * DD + h * DK + c0;
            const float* vsrc = Vp + (size_t)(b * SS + k0 + r) * DD + h * DK + c0;
            uint32_t* kdst = (uint32_t*)&Ks[r * AT_PADH + c0];
#pragma unroll
            for (int i = 0; i < 4; i++) {
                float4 kv = *(const float4*)(ksrc + 4 * i);
                kdst[2 * i] = packh2(kv.x, kv.y);
                kdst[2 * i + 1] = packh2(kv.z, kv.w);
                float4 vv = *(const float4*)(vsrc + 4 * i);
                const int c = c0 + 4 * i;
                Vt[(c + 0) * AT_PADH + r] = __float2half_rn(vv.x);
                Vt[(c + 1) * AT_PADH + r] = __float2half_rn(vv.y);
                Vt[(c + 2) * AT_PADH + r] = __float2half_rn(vv.z);
                Vt[(c + 3) * AT_PADH + r] = __float2half_rn(vv.w);
            }
        }
        if (t < 64) Ms[t] = Mp[b * SS + k0 + t];
        __syncthreads();

        // ---- S = Q K^T : 4 k16-steps x 8 n-frags ----
        float S[8][4];
#pragma unroll
        for (int nf = 0; nf < 8; nf++)
#pragma unroll
            for (int j = 0; j < 4; j++) S[nf][j] = 0.0f;
#pragma unroll
        for (int ks = 0; ks < 4; ks++) {
            const int kw = ks * 8 + tig;
            uint32_t a[4];
            a[0] = Q32[(16 * wid + g) * AT_WS + kw];
            a[1] = Q32[(16 * wid + g + 8) * AT_WS + kw];
            a[2] = Q32[(16 * wid + g) * AT_WS + kw + 4];
            a[3] = Q32[(16 * wid + g + 8) * AT_WS + kw + 4];
#pragma unroll
            for (int nf = 0; nf < 8; nf++) {
                uint32_t bfr[2];
                bfr[0] = K32[(8 * nf + g) * AT_WS + kw];
                bfr[1] = K32[(8 * nf + g) * AT_WS + kw + 4];
                mma_f16(S[nf], a, bfr);
            }
        }

        // ---- scale + mask + warp-local online softmax ----
        const float scale = 0.125f;
        float mx0 = -1e30f, mx1 = -1e30f;
#pragma unroll
        for (int nf = 0; nf < 8; nf++) {
            const int cb = k0 + 8 * nf + 2 * tig;
            const int mk0 = Ms[8 * nf + 2 * tig];
            const int mk1 = Ms[8 * nf + 2 * tig + 1];
            float s0 = S[nf][0] * scale;
            float s1 = S[nf][1] * scale;
            float s2 = S[nf][2] * scale;
            float s3 = S[nf][3] * scale;
            if (mk0 == 0 && cb != rq0) s0 = -1e9f;
            if (mk1 == 0 && cb + 1 != rq0) s1 = -1e9f;
            if (mk0 == 0 && cb != rq1) s2 = -1e9f;
            if (mk1 == 0 && cb + 1 != rq1) s3 = -1e9f;
            S[nf][0] = s0; S[nf][1] = s1; S[nf][2] = s2; S[nf][3] = s3;
            mx0 = fmaxf(mx0, fmaxf(s0, s1));
            mx1 = fmaxf(mx1, fmaxf(s2, s3));
        }
        mx0 = fmaxf(mx0, __shfl_xor_sync(0xffffffffu, mx0, 1));
        mx0 = fmaxf(mx0, __shfl_xor_sync(0xffffffffu, mx0, 2));
        mx1 = fmaxf(mx1, __shfl_xor_sync(0xffffffffu, mx1, 1));
        mx1 = fmaxf(mx1, __shfl_xor_sync(0xffffffffu, mx1, 2));

        const float mn0 = fmaxf(m0r, mx0);
        const float mn1 = fmaxf(m1r, mx1);
        const float c0f = __expf(m0r - mn0);
        const float c1f = __expf(m1r - mn1);
        m0r = mn0; m1r = mn1;

        float rs0 = 0.0f, rs1 = 0.0f;
#pragma unroll
        for (int nf = 0; nf < 8; nf++) {
            float p0 = __expf(S[nf][0] - mn0);
            float p1 = __expf(S[nf][1] - mn0);
            float p2 = __expf(S[nf][2] - mn1);
            float p3 = __expf(S[nf][3] - mn1);
            S[nf][0] = p0; S[nf][1] = p1; S[nf][2] = p2; S[nf][3] = p3;
            rs0 += p0 + p1;
            rs1 += p2 + p3;
        }
        rs0 += __shfl_xor_sync(0xffffffffu, rs0, 1);
        rs0 += __shfl_xor_sync(0xffffffffu, rs0, 2);
        rs1 += __shfl_xor_sync(0xffffffffu, rs1, 1);
        rs1 += __shfl_xor_sync(0xffffffffu, rs1, 2);
        l0r = l0r * c0f + rs0;
        l1r = l1r * c1f + rs1;

#pragma unroll
        for (int d = 0; d < 8; d++) {
            O[d][0] *= c0f; O[d][1] *= c0f;
            O[d][2] *= c1f; O[d][3] *= c1f;
        }

        // ---- P = exp * group_prob -> fp16 -> smem ----
        {
            const float* Gb0 = Gp + ((size_t)b * SS + rq0) * SS + k0;
            const float* Gb1 = Gp + ((size_t)b * SS + rq1) * SS + k0;
            uint32_t* P0 = (uint32_t*)Ps + (16 * wid + g) * AT_WS;
            uint32_t* P1 = (uint32_t*)Ps + (16 * wid + g + 8) * AT_WS;
#pragma unroll
            for (int nf = 0; nf < 8; nf++) {
                const int cc = 8 * nf + 2 * tig;
                float2 g0 = *(const float2*)(Gb0 + cc);
                float2 g1 = *(const float2*)(Gb1 + cc);
                P0[nf * 4 + tig] = packh2(S[nf][0] * g0.x, S[nf][1] * g0.y);
                P1[nf * 4 + tig] = packh2(S[nf][2] * g1.x, S[nf][3] * g1.y);
            }
        }
        __syncwarp();

        // ---- O += P V : 4 k16-steps x 8 d-frags ----
#pragma unroll
        for (int ks = 0; ks < 4; ks++) {
            const int kw = ks * 8 + tig;
            uint32_t a[4];
            a[0] = P32[(16 * wid + g) * AT_WS + kw];
            a[1] = P32[(16 * wid + g + 8) * AT_WS + kw];
            a[2] = P32[(16 * wid + g) * AT_WS + kw + 4];
            a[3] = P32[(16 * wid + g + 8) * AT_WS + kw + 4];
#pragma unroll
            for (int df = 0; df < 8; df++) {
                uint32_t bfr[2];
                bfr[0] = V32[(8 * df + g) * AT_WS + kw];
                bfr[1] = V32[(8 * df + g) * AT_WS + kw + 4];
                mma_f16(O[df], a, bfr);
            }
        }
    }

    // ---- epilogue ----
    const float inv0 = 1.0f / l0r;
    const float inv1 = 1.0f / l1r;
    float* o0 = Op + (size_t)(b * SS + rq0) * DD + h * DK;
    float* o1 = Op + (size_t)(b * SS + rq1) * DD + h * DK;
#pragma unroll
    for (int df = 0; df < 8; df++) {
        const int c = 8 * df + 2 * tig;
        float2 v0 = make_float2(O[df][0] * inv0, O[df][1] * inv0);
        float2 v1 = make_float2(O[df][2] * inv1, O[df][3] * inv1);
        *(float2*)(o0 + c) = v0;
        *(float2*)(o1 + c) = v1;
    }
}

// ---------------------------------------------------------------------------
extern "C" void kernel_launch(void* const* d_in, const int* in_sizes, int n_in,
                              void* d_out, int out_size)
{
    const float* query = (const float*)d_in[0];
    const float* key   = (const float*)d_in[1];
    const float* value = (const float*)d_in[2];
    const float* gprob = (const float*)d_in[3];
    const int*   mask  = (const int*)d_in[4];
    const float* Wq = (const float*)d_in[5];
    const float* bq = (const float*)d_in[6];
    const float* Wk = (const float*)d_in[7];
    const float* bk = (const float*)d_in[8];
    const float* Wv = (const float*)d_in[9];
    const float* bv = (const float*)d_in[10];
    const float* Wo = (const float*)d_in[11];
    const float* bo = (const float*)d_in[12];
    float* out = (float*)d_out;

    float *gq, *gk, *gv, *gx;
    __half *ha, *hw;
    cudaGetSymbolAddress((void**)&gq, g_q);
    cudaGetSymbolAddress((void**)&gk, g_k);
    cudaGetSymbolAddress((void**)&gv, g_v);
    cudaGetSymbolAddress((void**)&gx, g_x);
    cudaGetSymbolAddress((void**)&ha, g_ha);
    cudaGetSymbolAddress((void**)&hw, g_hw);

    cudaFuncSetAttribute(gemm_tc, cudaFuncAttributeMaxDynamicSharedMemorySize, G_SMEM_TOTAL);
    cudaFuncSetAttribute(attn_tc, cudaFuncAttributeMaxDynamicSharedMemorySize, AT_SMEM_BYTES);

    const int AB = MROWS * DD / 8 / 256;  // 2048 blocks
    const int WB = DD * DD / 8 / 256;     // 512 blocks
    dim3 gg(DD / 128, MROWS / 128);       // (8, 32)

    cvt_half<<<AB, 256>>>(query, ha);
    cvt_half<<<WB, 256>>>(Wq, hw);
    gemm_tc<<<gg, 256, G_SMEM_TOTAL>>>(ha, hw, bq, gq);

    cvt_half<<<AB, 256>>>(key, ha);
    cvt_half<<<WB, 256>>>(Wk, hw);
    gemm_tc<<<gg, 256, G_SMEM_TOTAL>>>(ha, hw, bk, gk);

    cvt_half<<<AB, 256>>>(value, ha);
    cvt_half<<<WB, 256>>>(Wv, hw);
    gemm_tc<<<gg, 256, G_SMEM_TOTAL>>>(ha, hw, bv, gv);

    attn_tc<<<dim3(SS / 128, HH, BB), 256, AT_SMEM_BYTES>>>(gq, gk, gv, gprob, mask, gx);

    cvt_half<<<AB, 256>>>(gx, ha);
    cvt_half<<<WB, 256>>>(Wo, hw);
    gemm_tc<<<gg, 256, G_SMEM_TOTAL>>>(ha, hw, bo, out);
}

// round 8
// speedup vs baseline: 4.6292x; 1.4832x over previous
#include <cuda_runtime.h>
#include <cuda_fp16.h>
#include <cstdint>

// Problem constants
#define BB 2
#define SS 2048
#define DD 1024
#define HH 16
#define DK 64
#define MROWS 4096
#define MD (MROWS * DD)
#define NN (DD * DD)

// Scratch (alloc-free rule: __device__ globals), all fp16
__device__ __half g_in_h[3 * MD];   // query,key,value converted
__device__ __half g_w_h[4 * NN];    // Wq,Wk,Wv,Wo converted
__device__ __half g_qkv[3 * MD];    // projected Q,K,V
__device__ __half g_o_h[MD];        // attention output

// ---------------------------------------------------------------------------
// Helpers
// ---------------------------------------------------------------------------
__device__ __forceinline__ uint32_t smem_to_u32(const void* p) {
    uint32_t a;
    asm("{ .reg .u64 t; cvta.to.shared.u64 t, %1; cvt.u32.u64 %0, t; }" : "=r"(a) : "l"(p));
    return a;
}
__device__ __forceinline__ uint32_t packh2(float x, float y) {
    __half2 h = __floats2half2_rn(x, y);
    return *(uint32_t*)&h;
}
#define CP_ASYNC16(dst, src) \
    asm volatile("cp.async.cg.shared.global [%0], [%1], 16;" :: "r"((uint32_t)(dst)), "l"(src))
#define CP_COMMIT() asm volatile("cp.async.commit_group;" ::: "memory")
#define CP_WAIT2()  asm volatile("cp.async.wait_group 2;" ::: "memory")
#define CP_WAIT0()  asm volatile("cp.async.wait_group 0;" ::: "memory")

__device__ __forceinline__ void mma_f16(float* c, const uint32_t* a, const uint32_t* b) {
    asm volatile(
        "mma.sync.aligned.m16n8k16.row.col.f32.f16.f16.f32 "
        "{%0,%1,%2,%3}, {%4,%5,%6,%7}, {%8,%9}, {%0,%1,%2,%3};"
        : "+f"(c[0]), "+f"(c[1]), "+f"(c[2]), "+f"(c[3])
        : "r"(a[0]), "r"(a[1]), "r"(a[2]), "r"(a[3]), "r"(b[0]), "r"(b[1]));
}
__device__ __forceinline__ void ldsm4(uint32_t* r, uint32_t a) {
    asm volatile("ldmatrix.sync.aligned.m8n8.x4.shared.b16 {%0,%1,%2,%3}, [%4];"
        : "=r"(r[0]), "=r"(r[1]), "=r"(r[2]), "=r"(r[3]) : "r"(a));
}
__device__ __forceinline__ void ldsm4t(uint32_t* r, uint32_t a) {
    asm volatile("ldmatrix.sync.aligned.m8n8.x4.trans.shared.b16 {%0,%1,%2,%3}, [%4];"
        : "=r"(r[0]), "=r"(r[1]), "=r"(r[2]), "=r"(r[3]) : "r"(a));
}

// ---------------------------------------------------------------------------
// Batched fp32 -> fp16 convert (z selects tensor)
// ---------------------------------------------------------------------------
struct CvtArgs { const float* src[4]; __half* dst[4]; };

__global__ __launch_bounds__(256) void cvt_half(CvtArgs args) {
    const float* in = args.src[blockIdx.z];
    __half* out = args.dst[blockIdx.z];
    int i = (blockIdx.x * 256 + threadIdx.x) * 8;
    float4 v0 = *(const float4*)(in + i);
    float4 v1 = *(const float4*)(in + i + 4);
    uint4 o;
    o.x = packh2(v0.x, v0.y);
    o.y = packh2(v0.z, v0.w);
    o.z = packh2(v1.x, v1.y);
    o.w = packh2(v1.z, v1.w);
    *(uint4*)(out + i) = o;
}

// ---------------------------------------------------------------------------
// fp16 GEMM body: C[M,N] = A[M,K] * W[N,K]^T + bias   (M=4096, N=K=1024)
// 128x128x32 tiles, 256 threads (8 warps 2x4), warp tile 64x32, ldmatrix frags.
// Smem pad: 40 halves/row (80B) -> ldmatrix conflict-free.
// ---------------------------------------------------------------------------
#define G_NS 4
#define G_ROWB 80
#define G_TILE_B (128 * G_ROWB)            // 10240
#define G_STAGE_B (2 * G_TILE_B)           // 20480
#define G_SMEM_TOTAL (G_NS * G_STAGE_B)    // 81920

template <typename OutT>
__device__ __forceinline__ void gemm_body(
    const __half* __restrict__ A, const __half* __restrict__ W,
    const float* __restrict__ bias, OutT* __restrict__ C, char* smem)
{
    const uint32_t sb = smem_to_u32(smem);
    const int t = threadIdx.x;
    const int wid = t >> 5, lane = t & 31;
    const int g = lane >> 2, tig = lane & 3;
    const int wm = wid >> 2, wn = wid & 3;
    const int m0 = blockIdx.y * 128, n0 = blockIdx.x * 128;
    const int K = DD;

    const __half* Ab = A + (size_t)m0 * K;
    const __half* Wb = W + (size_t)n0 * K;

    const int lrow = t >> 1;
    const int cp = (t & 1) * 2;

    auto load_stage = [&](int s, int kt) {
        uint32_t sa = sb + s * G_STAGE_B + lrow * G_ROWB + cp * 16;
        uint32_t sw = sa + G_TILE_B;
        const __half* ga = Ab + (size_t)lrow * K + kt * 32 + cp * 8;
        const __half* gw = Wb + (size_t)lrow * K + kt * 32 + cp * 8;
        CP_ASYNC16(sa, ga);
        CP_ASYNC16(sa + 16, ga + 8);
        CP_ASYNC16(sw, gw);
        CP_ASYNC16(sw + 16, gw + 8);
    };

    // ldmatrix lane offsets (bytes)
    const uint32_t aoff = (uint32_t)((wm * 64 + (lane & 15)) * G_ROWB + (lane >> 4) * 16);
    const uint32_t boff = (uint32_t)((wn * 32 + (lane & 7) + (lane >> 4) * 8) * G_ROWB
                                     + ((lane >> 3) & 1) * 16);

    float acc[4][4][4];
#pragma unroll
    for (int i = 0; i < 4; i++)
#pragma unroll
        for (int j = 0; j < 4; j++)
#pragma unroll
            for (int k = 0; k < 4; k++) acc[i][j][k] = 0.0f;

    const int NT = K / 32;
    for (int s = 0; s < G_NS - 1; s++) { load_stage(s, s); CP_COMMIT(); }

    for (int kt = 0; kt < NT; kt++) {
        CP_WAIT2();
        __syncthreads();
        {
            const uint32_t sA = sb + (kt & 3) * G_STAGE_B;
            const uint32_t sW = sA + G_TILE_B;
#pragma unroll
            for (int ks = 0; ks < 2; ks++) {
                uint32_t a[4][4], b[4][2];
#pragma unroll
                for (int mf = 0; mf < 4; mf++)
                    ldsm4(a[mf], sA + aoff + mf * (16 * G_ROWB) + ks * 32);
#pragma unroll
                for (int np = 0; np < 2; np++) {
                    uint32_t t4[4];
                    ldsm4(t4, sW + boff + np * (16 * G_ROWB) + ks * 32);
                    b[2 * np][0] = t4[0]; b[2 * np][1] = t4[1];
                    b[2 * np + 1][0] = t4[2]; b[2 * np + 1][1] = t4[3];
                }
#pragma unroll
                for (int mf = 0; mf < 4; mf++)
#pragma unroll
                    for (int nf = 0; nf < 4; nf++)
                        mma_f16(acc[mf][nf], a[mf], b[nf]);
            }
        }
        __syncthreads();
        const int nx = kt + G_NS - 1;
        if (nx < NT) { load_stage(nx & 3, nx); CP_COMMIT(); }
    }

#pragma unroll
    for (int mf = 0; mf < 4; mf++) {
        const int r = m0 + wm * 64 + mf * 16 + g;
#pragma unroll
        for (int nf = 0; nf < 4; nf++) {
            const int c = n0 + wn * 32 + nf * 8 + tig * 2;
            const float b0 = bias[c], b1 = bias[c + 1];
            if constexpr (sizeof(OutT) == 2) {
                __half2* p0 = (__half2*)&C[(size_t)r * DD + c];
                __half2* p1 = (__half2*)&C[(size_t)(r + 8) * DD + c];
                *p0 = __floats2half2_rn(acc[mf][nf][0] + b0, acc[mf][nf][1] + b1);
                *p1 = __floats2half2_rn(acc[mf][nf][2] + b0, acc[mf][nf][3] + b1);
            } else {
                *(float2*)&C[(size_t)r * DD + c] =
                    make_float2(acc[mf][nf][0] + b0, acc[mf][nf][1] + b1);
                *(float2*)&C[(size_t)(r + 8) * DD + c] =
                    make_float2(acc[mf][nf][2] + b0, acc[mf][nf][3] + b1);
            }
        }
    }
}

struct ProjArgs {
    const __half* A[3];
    const __half* W[3];
    const float* bias[3];
    __half* C[3];
};

__global__ __launch_bounds__(256, 2) void gemm_proj(ProjArgs args) {
    extern __shared__ __align__(128) char smem[];
    const int z = blockIdx.z;
    gemm_body<__half>(args.A[z], args.W[z], args.bias[z], args.C[z], smem);
}

__global__ __launch_bounds__(256, 2) void gemm_out(
    const __half* __restrict__ A, const __half* __restrict__ W,
    const float* __restrict__ bias, float* __restrict__ C) {
    extern __shared__ __align__(128) char smem[];
    gemm_body<float>(A, W, bias, C, smem);
}

// ---------------------------------------------------------------------------
// fp16 flash attention, ldmatrix fragments, cp.async loads, half in/out.
// Block: 128 q-rows x (b,h); 8 warps; warp w owns q-rows [16w,16w+16).
// Smem row stride 72 halves (144B -> ldmatrix conflict-free, 16B aligned).
// V stored naturally; PV B-frags via ldmatrix.trans.
// ---------------------------------------------------------------------------
#define AT_PADH 72
#define AT_ROWB 144
#define AT_WS 36
#define AT_QS 0
#define AT_KS (128 * AT_PADH)
#define AT_VS (AT_KS + 64 * AT_PADH)
#define AT_PS (AT_VS + 64 * AT_PADH)
#define AT_HALVES (AT_PS + 128 * AT_PADH)
#define AT_SMEM_BYTES (AT_HALVES * 2 + 256)

__global__ __launch_bounds__(256, 2) void attn_tc(
    const __half* __restrict__ Qp, const __half* __restrict__ Kp,
    const __half* __restrict__ Vp, const float* __restrict__ Gp,
    const int* __restrict__ Mp, __half* __restrict__ Op)
{
    extern __shared__ __align__(16) __half smh[];
    const uint32_t sb = smem_to_u32(smh);
    const uint32_t sQ = sb;
    const uint32_t sK = sb + AT_KS * 2;
    const uint32_t sV = sb + AT_VS * 2;
    const uint32_t sP = sb + AT_PS * 2;
    int* Ms = (int*)(smh + AT_HALVES);

    const int b = blockIdx.z, h = blockIdx.y;
    const int q0 = blockIdx.x * 128;
    const int t = threadIdx.x;
    const int wid = t >> 5, lane = t & 31;
    const int g = lane >> 2, tig = lane & 3;

    // ---- Q tile via cp.async ----
    {
        const int r = t >> 1, c0 = (t & 1) * 32;
        const __half* src = Qp + (size_t)(b * SS + q0 + r) * DD + h * DK + c0;
        uint32_t dst = sQ + r * AT_ROWB + c0 * 2;
        CP_ASYNC16(dst, src);
        CP_ASYNC16(dst + 16, src + 8);
        CP_ASYNC16(dst + 32, src + 16);
        CP_ASYNC16(dst + 48, src + 24);
        CP_COMMIT();
    }

    float m0r = -1e30f, m1r = -1e30f;
    float l0r = 0.0f, l1r = 0.0f;
    float O[8][4];
#pragma unroll
    for (int d = 0; d < 8; d++)
#pragma unroll
        for (int j = 0; j < 4; j++) O[d][j] = 0.0f;

    const int rq0 = q0 + 16 * wid + g;
    const int rq1 = rq0 + 8;

    // ldmatrix lane offsets (bytes)
    const uint32_t qoff = (uint32_t)((16 * wid + (lane & 15)) * AT_ROWB + (lane >> 4) * 16);
    const uint32_t koff = (uint32_t)(((lane & 7) + (lane >> 4) * 8) * AT_ROWB
                                     + ((lane >> 3) & 1) * 16);
    const uint32_t voff = (uint32_t)(((lane & 7) + ((lane >> 3) & 1) * 8) * AT_ROWB
                                     + (lane >> 4) * 16);

    for (int k0 = 0; k0 < SS; k0 += 64) {
        __syncthreads();  // prior tile done with K/V
        // ---- K and V tiles via cp.async (natural layout) ----
        {
            const int r = t >> 2, c0 = (t & 3) * 16;
            const __half* ksrc = Kp + (size_t)(b * SS + k0 + r) * DD + h * DK + c0;
            const __half* vsrc = Vp + (size_t)(b * SS + k0 + r) * DD + h * DK + c0;
            uint32_t kd = sK + r * AT_ROWB + c0 * 2;
            uint32_t vd = sV + r * AT_ROWB + c0 * 2;
            CP_ASYNC16(kd, ksrc);
            CP_ASYNC16(kd + 16, ksrc + 8);
            CP_ASYNC16(vd, vsrc);
            CP_ASYNC16(vd + 16, vsrc + 8);
            CP_COMMIT();
        }
        if (t < 64) Ms[t] = Mp[b * SS + k0 + t];
        CP_WAIT0();
        __syncthreads();

        // ---- S = Q K^T ----
        float S[8][4];
#pragma unroll
        for (int nf = 0; nf < 8; nf++)
#pragma unroll
            for (int j = 0; j < 4; j++) S[nf][j] = 0.0f;
#pragma unroll
        for (int ks = 0; ks < 4; ks++) {
            uint32_t a[4];
            ldsm4(a, sQ + qoff + ks * 32);
#pragma unroll
            for (int np = 0; np < 4; np++) {
                uint32_t t4[4];
                ldsm4(t4, sK + koff + np * (16 * AT_ROWB) + ks * 32);
                mma_f16(S[2 * np], a, t4);
                mma_f16(S[2 * np + 1], a, t4 + 2);
            }
        }

        // ---- scale + mask + warp-local online softmax ----
        const float scale = 0.125f;
        float mx0 = -1e30f, mx1 = -1e30f;
#pragma unroll
        for (int nf = 0; nf < 8; nf++) {
            const int cb = k0 + 8 * nf + 2 * tig;
            const int mk0 = Ms[8 * nf + 2 * tig];
            const int mk1 = Ms[8 * nf + 2 * tig + 1];
            float s0 = S[nf][0] * scale;
            float s1 = S[nf][1] * scale;
            float s2 = S[nf][2] * scale;
            float s3 = S[nf][3] * scale;
            if (mk0 == 0 && cb != rq0) s0 = -1e9f;
            if (mk1 == 0 && cb + 1 != rq0) s1 = -1e9f;
            if (mk0 == 0 && cb != rq1) s2 = -1e9f;
            if (mk1 == 0 && cb + 1 != rq1) s3 = -1e9f;
            S[nf][0] = s0; S[nf][1] = s1; S[nf][2] = s2; S[nf][3] = s3;
            mx0 = fmaxf(mx0, fmaxf(s0, s1));
            mx1 = fmaxf(mx1, fmaxf(s2, s3));
        }
        mx0 = fmaxf(mx0, __shfl_xor_sync(0xffffffffu, mx0, 1));
        mx0 = fmaxf(mx0, __shfl_xor_sync(0xffffffffu, mx0, 2));
        mx1 = fmaxf(mx1, __shfl_xor_sync(0xffffffffu, mx1, 1));
        mx1 = fmaxf(mx1, __shfl_xor_sync(0xffffffffu, mx1, 2));

        const float mn0 = fmaxf(m0r, mx0);
        const float mn1 = fmaxf(m1r, mx1);
        const float c0f = __expf(m0r - mn0);
        const float c1f = __expf(m1r - mn1);
        m0r = mn0; m1r = mn1;

        float rs0 = 0.0f, rs1 = 0.0f;
#pragma unroll
        for (int nf = 0; nf < 8; nf++) {
            float p0 = __expf(S[nf][0] - mn0);
            float p1 = __expf(S[nf][1] - mn0);
            float p2 = __expf(S[nf][2] - mn1);
            float p3 = __expf(S[nf][3] - mn1);
            S[nf][0] = p0; S[nf][1] = p1; S[nf][2] = p2; S[nf][3] = p3;
            rs0 += p0 + p1;
            rs1 += p2 + p3;
        }
        rs0 += __shfl_xor_sync(0xffffffffu, rs0, 1);
        rs0 += __shfl_xor_sync(0xffffffffu, rs0, 2);
        rs1 += __shfl_xor_sync(0xffffffffu, rs1, 1);
        rs1 += __shfl_xor_sync(0xffffffffu, rs1, 2);
        l0r = l0r * c0f + rs0;
        l1r = l1r * c1f + rs1;

#pragma unroll
        for (int d = 0; d < 8; d++) {
            O[d][0] *= c0f; O[d][1] *= c0f;
            O[d][2] *= c1f; O[d][3] *= c1f;
        }

        // ---- P = exp * group_prob -> fp16 -> smem ----
        {
            const float* Gb0 = Gp + ((size_t)b * SS + rq0) * SS + k0;
            const float* Gb1 = Gp + ((size_t)b * SS + rq1) * SS + k0;
            uint32_t* P0 = (uint32_t*)smh + AT_PS / 2 + (16 * wid + g) * AT_WS;
            uint32_t* P1 = P0 + 8 * AT_WS;
#pragma unroll
            for (int nf = 0; nf < 8; nf++) {
                const int cc = 8 * nf + 2 * tig;
                float2 g0 = *(const float2*)(Gb0 + cc);
                float2 g1 = *(const float2*)(Gb1 + cc);
                P0[nf * 4 + tig] = packh2(S[nf][0] * g0.x, S[nf][1] * g0.y);
                P1[nf * 4 + tig] = packh2(S[nf][2] * g1.x, S[nf][3] * g1.y);
            }
        }
        __syncwarp();

        // ---- O += P V (V natural; B-frags via ldmatrix.trans) ----
#pragma unroll
        for (int ks = 0; ks < 4; ks++) {
            uint32_t a[4];
            ldsm4(a, sP + qoff + ks * 32);
#pragma unroll
            for (int dp = 0; dp < 4; dp++) {
                uint32_t t4[4];
                ldsm4t(t4, sV + voff + ks * (16 * AT_ROWB) + dp * 32);
                mma_f16(O[2 * dp], a, t4);
                mma_f16(O[2 * dp + 1], a, t4 + 2);
            }
        }
    }

    // ---- epilogue: normalize, store half ----
    const float inv0 = 1.0f / l0r;
    const float inv1 = 1.0f / l1r;
    __half* o0 = Op + (size_t)(b * SS + rq0) * DD + h * DK;
    __half* o1 = Op + (size_t)(b * SS + rq1) * DD + h * DK;
#pragma unroll
    for (int df = 0; df < 8; df++) {
        const int c = 8 * df + 2 * tig;
        *(__half2*)(o0 + c) = __floats2half2_rn(O[df][0] * inv0, O[df][1] * inv0);
        *(__half2*)(o1 + c) = __floats2half2_rn(O[df][2] * inv1, O[df][3] * inv1);
    }
}

// ---------------------------------------------------------------------------
extern "C" void kernel_launch(void* const* d_in, const int* in_sizes, int n_in,
                              void* d_out, int out_size)
{
    const float* query = (const float*)d_in[0];
    const float* key   = (const float*)d_in[1];
    const float* value = (const float*)d_in[2];
    const float* gprob = (const float*)d_in[3];
    const int*   mask  = (const int*)d_in[4];
    const float* Wq = (const float*)d_in[5];
    const float* bq = (const float*)d_in[6];
    const float* Wk = (const float*)d_in[7];
    const float* bk = (const float*)d_in[8];
    const float* Wv = (const float*)d_in[9];
    const float* bv = (const float*)d_in[10];
    const float* Wo = (const float*)d_in[11];
    const float* bo = (const float*)d_in[12];
    float* out = (float*)d_out;

    __half *in_h, *w_h, *qkv, *o_h;
    cudaGetSymbolAddress((void**)&in_h, g_in_h);
    cudaGetSymbolAddress((void**)&w_h, g_w_h);
    cudaGetSymbolAddress((void**)&qkv, g_qkv);
    cudaGetSymbolAddress((void**)&o_h, g_o_h);

    cudaFuncSetAttribute(gemm_proj, cudaFuncAttributeMaxDynamicSharedMemorySize, G_SMEM_TOTAL);
    cudaFuncSetAttribute(gemm_out, cudaFuncAttributeMaxDynamicSharedMemorySize, G_SMEM_TOTAL);
    cudaFuncSetAttribute(attn_tc, cudaFuncAttributeMaxDynamicSharedMemorySize, AT_SMEM_BYTES);

    // convert activations (z=3) and weights (z=4)
    CvtArgs ca;
    ca.src[0] = query; ca.src[1] = key; ca.src[2] = value; ca.src[3] = query;
    ca.dst[0] = in_h; ca.dst[1] = in_h + MD; ca.dst[2] = in_h + 2 * MD; ca.dst[3] = in_h;
    cvt_half<<<dim3(MD / 8 / 256, 1, 3), 256>>>(ca);

    CvtArgs cw;
    cw.src[0] = Wq; cw.src[1] = Wk; cw.src[2] = Wv; cw.src[3] = Wo;
    cw.dst[0] = w_h; cw.dst[1] = w_h + NN; cw.dst[2] = w_h + 2 * NN; cw.dst[3] = w_h + 3 * NN;
    cvt_half<<<dim3(NN / 8 / 256, 1, 4), 256>>>(cw);

    // fused Q/K/V projection
    ProjArgs pa;
    for (int i = 0; i < 3; i++) {
        pa.A[i] = in_h + (size_t)i * MD;
        pa.W[i] = w_h + (size_t)i * NN;
        pa.C[i] = qkv + (size_t)i * MD;
    }
    pa.bias[0] = bq; pa.bias[1] = bk; pa.bias[2] = bv;
    gemm_proj<<<dim3(DD / 128, MROWS / 128, 3), 256, G_SMEM_TOTAL>>>(pa);

    attn_tc<<<dim3(SS / 128, HH, BB), 256, AT_SMEM_BYTES>>>(
        qkv, qkv + MD, qkv + 2 * MD, gprob, mask, o_h);

    gemm_out<<<dim3(DD / 128, MROWS / 128), 256, G_SMEM_TOTAL>>>(
        o_h, w_h + 3 * NN, bo, out);
}

// round 11
// speedup vs baseline: 4.8820x; 1.0546x over previous
#include <cuda_runtime.h>
#include <cuda_fp16.h>
#include <cstdint>

// Problem constants
#define BB 2
#define SS 2048
#define DD 1024
#define HH 16
#define DK 64
#define MROWS 4096
#define MD (MROWS * DD)
#define NN (DD * DD)
#define GG (BB * SS * SS)

// Scratch (alloc-free rule: __device__ globals), all fp16
__device__ __half g_in_h[3 * MD];   // query,key,value converted
__device__ __half g_w_h[4 * NN];    // Wq,Wk,Wv,Wo converted
__device__ __half g_qkv[3 * MD];    // projected Q,K,V
__device__ __half g_o_h[MD];        // attention output
__device__ __half g_gh[GG];         // group_prob fp16

// ---------------------------------------------------------------------------
// Helpers
// ---------------------------------------------------------------------------
__device__ __forceinline__ uint32_t smem_to_u32(const void* p) {
    uint32_t a;
    asm("{ .reg .u64 t; cvta.to.shared.u64 t, %1; cvt.u32.u64 %0, t; }" : "=r"(a) : "l"(p));
    return a;
}
__device__ __forceinline__ uint32_t packh2(float x, float y) {
    __half2 h = __floats2half2_rn(x, y);
    return *(uint32_t*)&h;
}
__device__ __forceinline__ float fex2(float x) {
    float r; asm("ex2.approx.f32 %0, %1;" : "=f"(r) : "f"(x)); return r;
}
__device__ __forceinline__ uint32_t h2ex2(uint32_t x) {
    uint32_t r; asm("ex2.approx.f16x2 %0, %1;" : "=r"(r) : "r"(x)); return r;
}
__device__ __forceinline__ uint32_t h2mul(uint32_t a, uint32_t b) {
    uint32_t r; asm("mul.f16x2 %0, %1, %2;" : "=r"(r) : "r"(a), "r"(b)); return r;
}
#define CP_ASYNC16(dst, src) \
    asm volatile("cp.async.cg.shared.global [%0], [%1], 16;" :: "r"((uint32_t)(dst)), "l"(src))
#define CP_COMMIT() asm volatile("cp.async.commit_group;" ::: "memory")
#define CP_WAIT2()  asm volatile("cp.async.wait_group 2;" ::: "memory")
#define CP_WAIT1()  asm volatile("cp.async.wait_group 1;" ::: "memory")
#define CP_WAIT0()  asm volatile("cp.async.wait_group 0;" ::: "memory")

__device__ __forceinline__ void mma_f16(float* c, const uint32_t* a, const uint32_t* b) {
    asm volatile(
        "mma.sync.aligned.m16n8k16.row.col.f32.f16.f16.f32 "
        "{%0,%1,%2,%3}, {%4,%5,%6,%7}, {%8,%9}, {%0,%1,%2,%3};"
        : "+f"(c[0]), "+f"(c[1]), "+f"(c[2]), "+f"(c[3])
        : "r"(a[0]), "r"(a[1]), "r"(a[2]), "r"(a[3]), "r"(b[0]), "r"(b[1]));
}
__device__ __forceinline__ void ldsm4(uint32_t* r, uint32_t a) {
    asm volatile("ldmatrix.sync.aligned.m8n8.x4.shared.b16 {%0,%1,%2,%3}, [%4];"
        : "=r"(r[0]), "=r"(r[1]), "=r"(r[2]), "=r"(r[3]) : "r"(a));
}
__device__ __forceinline__ void ldsm4t(uint32_t* r, uint32_t a) {
    asm volatile("ldmatrix.sync.aligned.m8n8.x4.trans.shared.b16 {%0,%1,%2,%3}, [%4];"
        : "=r"(r[0]), "=r"(r[1]), "=r"(r[2]), "=r"(r[3]) : "r"(a));
}

// ---------------------------------------------------------------------------
// Batched fp32 -> fp16 convert
// ---------------------------------------------------------------------------
struct CvtArgs { const float* src[4]; __half* dst[4]; };

__global__ __launch_bounds__(256) void cvt_half(CvtArgs args) {
    const float* in = args.src[blockIdx.z];
    __half* out = args.dst[blockIdx.z];
    int i = (blockIdx.x * 256 + threadIdx.x) * 8;
    float4 v0 = *(const float4*)(in + i);
    float4 v1 = *(const float4*)(in + i + 4);
    uint4 o;
    o.x = packh2(v0.x, v0.y);
    o.y = packh2(v0.z, v0.w);
    o.z = packh2(v1.x, v1.y);
    o.w = packh2(v1.z, v1.w);
    *(uint4*)(out + i) = o;
}

// ---------------------------------------------------------------------------
// fp16 GEMM body (unchanged): C = A * W^T + bias, ldmatrix frags.
// ---------------------------------------------------------------------------
#define G_NS 4
#define G_ROWB 80
#define G_TILE_B (128 * G_ROWB)
#define G_STAGE_B (2 * G_TILE_B)
#define G_SMEM_TOTAL (G_NS * G_STAGE_B)

template <typename OutT>
__device__ __forceinline__ void gemm_body(
    const __half* __restrict__ A, const __half* __restrict__ W,
    const float* __restrict__ bias, OutT* __restrict__ C, char* smem)
{
    const uint32_t sb = smem_to_u32(smem);
    const int t = threadIdx.x;
    const int wid = t >> 5, lane = t & 31;
    const int g = lane >> 2, tig = lane & 3;
    const int wm = wid >> 2, wn = wid & 3;
    const int m0 = blockIdx.y * 128, n0 = blockIdx.x * 128;
    const int K = DD;

    const __half* Ab = A + (size_t)m0 * K;
    const __half* Wb = W + (size_t)n0 * K;

    const int lrow = t >> 1;
    const int cp = (t & 1) * 2;

    auto load_stage = [&](int s, int kt) {
        uint32_t sa = sb + s * G_STAGE_B + lrow * G_ROWB + cp * 16;
        uint32_t sw = sa + G_TILE_B;
        const __half* ga = Ab + (size_t)lrow * K + kt * 32 + cp * 8;
        const __half* gw = Wb + (size_t)lrow * K + kt * 32 + cp * 8;
        CP_ASYNC16(sa, ga);
        CP_ASYNC16(sa + 16, ga + 8);
        CP_ASYNC16(sw, gw);
        CP_ASYNC16(sw + 16, gw + 8);
    };

    const uint32_t aoff = (uint32_t)((wm * 64 + (lane & 15)) * G_ROWB + (lane >> 4) * 16);
    const uint32_t boff = (uint32_t)((wn * 32 + (lane & 7) + (lane >> 4) * 8) * G_ROWB
                                     + ((lane >> 3) & 1) * 16);

    float acc[4][4][4];
#pragma unroll
    for (int i = 0; i < 4; i++)
#pragma unroll
        for (int j = 0; j < 4; j++)
#pragma unroll
            for (int k = 0; k < 4; k++) acc[i][j][k] = 0.0f;

    const int NT = K / 32;
    for (int s = 0; s < G_NS - 1; s++) { load_stage(s, s); CP_COMMIT(); }

    for (int kt = 0; kt < NT; kt++) {
        CP_WAIT2();
        __syncthreads();
        {
            const uint32_t sA = sb + (kt & 3) * G_STAGE_B;
            const uint32_t sW = sA + G_TILE_B;
#pragma unroll
            for (int ks = 0; ks < 2; ks++) {
                uint32_t a[4][4], b[4][2];
#pragma unroll
                for (int mf = 0; mf < 4; mf++)
                    ldsm4(a[mf], sA + aoff + mf * (16 * G_ROWB) + ks * 32);
#pragma unroll
                for (int np = 0; np < 2; np++) {
                    uint32_t t4[4];
                    ldsm4(t4, sW + boff + np * (16 * G_ROWB) + ks * 32);
                    b[2 * np][0] = t4[0]; b[2 * np][1] = t4[1];
                    b[2 * np + 1][0] = t4[2]; b[2 * np + 1][1] = t4[3];
                }
#pragma unroll
                for (int mf = 0; mf < 4; mf++)
#pragma unroll
                    for (int nf = 0; nf < 4; nf++)
                        mma_f16(acc[mf][nf], a[mf], b[nf]);
            }
        }
        __syncthreads();
        const int nx = kt + G_NS - 1;
        if (nx < NT) { load_stage(nx & 3, nx); CP_COMMIT(); }
    }

#pragma unroll
    for (int mf = 0; mf < 4; mf++) {
        const int r = m0 + wm * 64 + mf * 16 + g;
#pragma unroll
        for (int nf = 0; nf < 4; nf++) {
            const int c = n0 + wn * 32 + nf * 8 + tig * 2;
            const float b0 = bias[c], b1 = bias[c + 1];
            if constexpr (sizeof(OutT) == 2) {
                __half2* p0 = (__half2*)&C[(size_t)r * DD + c];
                __half2* p1 = (__half2*)&C[(size_t)(r + 8) * DD + c];
                *p0 = __floats2half2_rn(acc[mf][nf][0] + b0, acc[mf][nf][1] + b1);
                *p1 = __floats2half2_rn(acc[mf][nf][2] + b0, acc[mf][nf][3] + b1);
            } else {
                *(float2*)&C[(size_t)r * DD + c] =
                    make_float2(acc[mf][nf][0] + b0, acc[mf][nf][1] + b1);
                *(float2*)&C[(size_t)(r + 8) * DD + c] =
                    make_float2(acc[mf][nf][2] + b0, acc[mf][nf][3] + b1);
            }
        }
    }
}

struct ProjArgs {
    const __half* A[3];
    const __half* W[3];
    const float* bias[3];
    __half* C[3];
};

__global__ __launch_bounds__(256, 2) void gemm_proj(ProjArgs args) {
    extern __shared__ __align__(128) char smem[];
    const int z = blockIdx.z;
    gemm_body<__half>(args.A[z], args.W[z], args.bias[z], args.C[z], smem);
}

__global__ __launch_bounds__(256, 2) void gemm_out(
    const __half* __restrict__ A, const __half* __restrict__ W,
    const float* __restrict__ bias, float* __restrict__ C) {
    extern __shared__ __align__(128) char smem[];
    gemm_body<float>(A, W, bias, C, smem);
}

// ---------------------------------------------------------------------------
// fp16 flash attention v2.1: P in registers, Q frags hoisted, K/V double-
// buffered, fp16x2 exp, l via ones-column MMA fed with E (exp ONLY — the
// group_prob multiply happens after the l accumulation; reference normalizes
// by sum(exp), not sum(exp*G)).
// ---------------------------------------------------------------------------
#define AT_ROWB 144
#define ATQ 0                       // 128*144 = 18432
#define ATK 18432                   // 2 x 64*144 = 18432
#define ATV 36864                   // 2 x 64*144 = 18432
#define ATMB 55296                  // 2048 floats = 8192
#define AT_SMEM_BYTES 63488
#define KV_BUF_B 9216

__global__ __launch_bounds__(256, 2) void attn_tc(
    const __half* __restrict__ Qp, const __half* __restrict__ Kp,
    const __half* __restrict__ Vp, const __half* __restrict__ Gh,
    const int* __restrict__ Mp, __half* __restrict__ Op)
{
    extern __shared__ __align__(16) char smc[];
    const uint32_t sb = smem_to_u32(smc);
    float* MB = (float*)(smc + ATMB);

    const int b = blockIdx.z, h = blockIdx.y;
    const int q0 = blockIdx.x * 128;
    const int t = threadIdx.x;
    const int wid = t >> 5, lane = t & 31;
    const int g = lane >> 2, tig = lane & 3;

    // ---- prologue: Q + KV(0) cp.async; mask bias by ALU ----
    {
        const int r = t >> 1, c0 = (t & 1) * 32;
        const __half* src = Qp + (size_t)(b * SS + q0 + r) * DD + h * DK + c0;
        uint32_t dst = sb + ATQ + r * AT_ROWB + c0 * 2;
        CP_ASYNC16(dst, src);
        CP_ASYNC16(dst + 16, src + 8);
        CP_ASYNC16(dst + 32, src + 16);
        CP_ASYNC16(dst + 48, src + 24);
    }
    {
        const int r = t >> 2, co = (t & 3) * 32;
        const __half* ksrc = Kp + (size_t)(b * SS + r) * DD + h * DK;
        const __half* vsrc = Vp + (size_t)(b * SS + r) * DD + h * DK;
        uint32_t kd = sb + ATK + r * AT_ROWB + co;
        uint32_t vd = sb + ATV + r * AT_ROWB + co;
        CP_ASYNC16(kd, ksrc + co / 2);
        CP_ASYNC16(kd + 16, ksrc + co / 2 + 8);
        CP_ASYNC16(vd, vsrc + co / 2);
        CP_ASYNC16(vd + 16, vsrc + co / 2 + 8);
    }
    CP_COMMIT();
    // mask -> log2-domain additive bias (0 or -1e5)
    for (int i = t; i < SS; i += 256)
        MB[i] = Mp[b * SS + i] ? 0.0f : -1e5f;

    const int rq0 = q0 + 16 * wid + g;
    const int rq1 = rq0 + 8;

    const uint32_t qoff = (uint32_t)((16 * wid + (lane & 15)) * AT_ROWB + (lane >> 4) * 16);
    const uint32_t koff = (uint32_t)(((lane & 7) + (lane >> 4) * 8) * AT_ROWB
                                     + ((lane >> 3) & 1) * 16);
    const uint32_t voff = (uint32_t)(((lane & 7) + ((lane >> 3) & 1) * 8) * AT_ROWB
                                     + (lane >> 4) * 16);
    const uint32_t bones = (g == 0) ? 0x3C003C00u : 0u;

    CP_WAIT0();
    __syncthreads();

    // hoist Q fragments (16 regs)
    uint32_t qf[4][4];
#pragma unroll
    for (int ks = 0; ks < 4; ks++) ldsm4(qf[ks], sb + ATQ + qoff + ks * 32);

    float m0r = -1e30f, m1r = -1e30f;
    float O[9][4];
#pragma unroll
    for (int d = 0; d < 9; d++)
#pragma unroll
        for (int j = 0; j < 4; j++) O[d][j] = 0.0f;

    const __half2* G0 = (const __half2*)(Gh + ((size_t)b * SS + rq0) * SS);
    const __half2* G1 = (const __half2*)(Gh + ((size_t)b * SS + rq1) * SS);
    const float CS = 0.1803368867f;  // 0.125 * log2(e)
    const int NKT = SS / 64;         // 32

    for (int it = 0; it < NKT; it++) {
        // prefetch next K/V tile into the other buffer
        if (it + 1 < NKT) {
            const int r = t >> 2, co = (t & 3) * 32;
            const int nk = (it + 1) * 64;
            const __half* ksrc = Kp + (size_t)(b * SS + nk + r) * DD + h * DK;
            const __half* vsrc = Vp + (size_t)(b * SS + nk + r) * DD + h * DK;
            const uint32_t bf = (uint32_t)((it + 1) & 1) * KV_BUF_B;
            uint32_t kd = sb + ATK + bf + r * AT_ROWB + co;
            uint32_t vd = sb + ATV + bf + r * AT_ROWB + co;
            CP_ASYNC16(kd, ksrc + co / 2);
            CP_ASYNC16(kd + 16, ksrc + co / 2 + 8);
            CP_ASYNC16(vd, vsrc + co / 2);
            CP_ASYNC16(vd + 16, vsrc + co / 2 + 8);
            CP_COMMIT();
            CP_WAIT1();
        } else {
            CP_WAIT0();
        }
        __syncthreads();

        const int k0 = it * 64;
        const uint32_t sKb = sb + ATK + (uint32_t)(it & 1) * KV_BUF_B;
        const uint32_t sVb = sb + ATV + (uint32_t)(it & 1) * KV_BUF_B;

        // ---- S = Q K^T ----
        float S[8][4];
#pragma unroll
        for (int nf = 0; nf < 8; nf++)
#pragma unroll
            for (int j = 0; j < 4; j++) S[nf][j] = 0.0f;
#pragma unroll
        for (int ks = 0; ks < 4; ks++) {
#pragma unroll
            for (int np = 0; np < 4; np++) {
                uint32_t t4[4];
                ldsm4(t4, sKb + koff + np * (16 * AT_ROWB) + ks * 32);
                mma_f16(S[2 * np], qf[ks], t4);
                mma_f16(S[2 * np + 1], qf[ks], t4 + 2);
            }
        }

        // ---- scale to log2 domain + mask bias + row max ----
        const bool diagT = (k0 < q0 + 128) && (k0 + 64 > q0);
        float mx0 = -1e30f, mx1 = -1e30f;
#pragma unroll
        for (int nf = 0; nf < 8; nf++) {
            const int cb = k0 + 8 * nf + 2 * tig;
            float2 mb = *(float2*)&MB[cb];
            float b00 = mb.x, b01 = mb.y, b10 = mb.x, b11 = mb.y;
            if (diagT) {
                if (cb == rq0) b00 = 0.0f;
                if (cb + 1 == rq0) b01 = 0.0f;
                if (cb == rq1) b10 = 0.0f;
                if (cb + 1 == rq1) b11 = 0.0f;
            }
            S[nf][0] = fmaf(S[nf][0], CS, b00);
            S[nf][1] = fmaf(S[nf][1], CS, b01);
            S[nf][2] = fmaf(S[nf][2], CS, b10);
            S[nf][3] = fmaf(S[nf][3], CS, b11);
            mx0 = fmaxf(mx0, fmaxf(S[nf][0], S[nf][1]));
            mx1 = fmaxf(mx1, fmaxf(S[nf][2], S[nf][3]));
        }
        mx0 = fmaxf(mx0, __shfl_xor_sync(0xffffffffu, mx0, 1));
        mx0 = fmaxf(mx0, __shfl_xor_sync(0xffffffffu, mx0, 2));
        mx1 = fmaxf(mx1, __shfl_xor_sync(0xffffffffu, mx1, 1));
        mx1 = fmaxf(mx1, __shfl_xor_sync(0xffffffffu, mx1, 2));

        const float mn0 = fmaxf(m0r, mx0);
        const float mn1 = fmaxf(m1r, mx1);
        const float c0f = fex2(m0r - mn0);
        const float c1f = fex2(m1r - mn1);
        m0r = mn0; m1r = mn1;

#pragma unroll
        for (int d = 0; d < 9; d++) {
            O[d][0] *= c0f; O[d][1] *= c0f;
            O[d][2] *= c1f; O[d][3] *= c1f;
        }

        // ---- E = 2^(s - m)  (fp16x2) — exp ONLY, no group_prob yet ----
        uint32_t Ea[8], Eb[8];
#pragma unroll
        for (int nf = 0; nf < 8; nf++) {
            Ea[nf] = h2ex2(packh2(S[nf][0] - mn0, S[nf][1] - mn0));
            Eb[nf] = h2ex2(packh2(S[nf][2] - mn1, S[nf][3] - mn1));
        }

        // ---- l += sum_k E  via ones-column MMA (denominator = sum exp) ----
#pragma unroll
        for (int ks = 0; ks < 4; ks++) {
            uint32_t a[4] = {Ea[2 * ks], Eb[2 * ks], Ea[2 * ks + 1], Eb[2 * ks + 1]};
            uint32_t bo[2] = {bones, bones};
            mma_f16(O[8], a, bo);
        }

        // ---- P = E * G in place ----
#pragma unroll
        for (int nf = 0; nf < 8; nf++) {
            const int ci = 4 * nf + tig;
            Ea[nf] = h2mul(Ea[nf], *(const uint32_t*)&G0[(size_t)(k0 / 2) + ci]);
            Eb[nf] = h2mul(Eb[nf], *(const uint32_t*)&G1[(size_t)(k0 / 2) + ci]);
        }

        // ---- O += P V ----
#pragma unroll
        for (int ks = 0; ks < 4; ks++) {
            uint32_t a[4] = {Ea[2 * ks], Eb[2 * ks], Ea[2 * ks + 1], Eb[2 * ks + 1]};
#pragma unroll
            for (int dp = 0; dp < 4; dp++) {
                uint32_t t4[4];
                ldsm4t(t4, sVb + voff + ks * (16 * AT_ROWB) + dp * 32);
                mma_f16(O[2 * dp], a, t4);
                mma_f16(O[2 * dp + 1], a, t4 + 2);
            }
        }
        __syncthreads();
    }

    // ---- epilogue: l from ones-frag (tig==0 holds col 64), normalize ----
    const float l0 = __shfl_sync(0xffffffffu, O[8][0], lane & ~3);
    const float l1 = __shfl_sync(0xffffffffu, O[8][2], lane & ~3);
    const float inv0 = 1.0f / l0;
    const float inv1 = 1.0f / l1;
    __half* o0 = Op + (size_t)(b * SS + rq0) * DD + h * DK;
    __half* o1 = Op + (size_t)(b * SS + rq1) * DD + h * DK;
#pragma unroll
    for (int df = 0; df < 8; df++) {
        const int c = 8 * df + 2 * tig;
        *(__half2*)(o0 + c) = __floats2half2_rn(O[df][0] * inv0, O[df][1] * inv0);
        *(__half2*)(o1 + c) = __floats2half2_rn(O[df][2] * inv1, O[df][3] * inv1);
    }
}

// ---------------------------------------------------------------------------
extern "C" void kernel_launch(void* const* d_in, const int* in_sizes, int n_in,
                              void* d_out, int out_size)
{
    const float* query = (const float*)d_in[0];
    const float* key   = (const float*)d_in[1];
    const float* value = (const float*)d_in[2];
    const float* gprob = (const float*)d_in[3];
    const int*   mask  = (const int*)d_in[4];
    const float* Wq = (const float*)d_in[5];
    const float* bq = (const float*)d_in[6];
    const float* Wk = (const float*)d_in[7];
    const float* bk = (const float*)d_in[8];
    const float* Wv = (const float*)d_in[9];
    const float* bv = (const float*)d_in[10];
    const float* Wo = (const float*)d_in[11];
    const float* bo = (const float*)d_in[12];
    float* out = (float*)d_out;

    __half *in_h, *w_h, *qkv, *o_h, *gh;
    cudaGetSymbolAddress((void**)&in_h, g_in_h);
    cudaGetSymbolAddress((void**)&w_h, g_w_h);
    cudaGetSymbolAddress((void**)&qkv, g_qkv);
    cudaGetSymbolAddress((void**)&o_h, g_o_h);
    cudaGetSymbolAddress((void**)&gh, g_gh);

    cudaFuncSetAttribute(gemm_proj, cudaFuncAttributeMaxDynamicSharedMemorySize, G_SMEM_TOTAL);
    cudaFuncSetAttribute(gemm_out, cudaFuncAttributeMaxDynamicSharedMemorySize, G_SMEM_TOTAL);
    cudaFuncSetAttribute(attn_tc, cudaFuncAttributeMaxDynamicSharedMemorySize, AT_SMEM_BYTES);

    // converts: activations (z=3), weights (z=4), group_prob (z=1)
    CvtArgs ca;
    ca.src[0] = query; ca.src[1] = key; ca.src[2] = value; ca.src[3] = query;
    ca.dst[0] = in_h; ca.dst[1] = in_h + MD; ca.dst[2] = in_h + 2 * MD; ca.dst[3] = in_h;
    cvt_half<<<dim3(MD / 8 / 256, 1, 3), 256>>>(ca);

    CvtArgs cw;
    cw.src[0] = Wq; cw.src[1] = Wk; cw.src[2] = Wv; cw.src[3] = Wo;
    cw.dst[0] = w_h; cw.dst[1] = w_h + NN; cw.dst[2] = w_h + 2 * NN; cw.dst[3] = w_h + 3 * NN;
    cvt_half<<<dim3(NN / 8 / 256, 1, 4), 256>>>(cw);

    CvtArgs cg;
    cg.src[0] = gprob; cg.dst[0] = gh;
    cvt_half<<<dim3(GG / 8 / 256, 1, 1), 256>>>(cg);

    // fused Q/K/V projection
    ProjArgs pa;
    for (int i = 0; i < 3; i++) {
        pa.A[i] = in_h + (size_t)i * MD;
        pa.W[i] = w_h + (size_t)i * NN;
        pa.C[i] = qkv + (size_t)i * MD;
    }
    pa.bias[0] = bq; pa.bias[1] = bk; pa.bias[2] = bv;
    gemm_proj<<<dim3(DD / 128, MROWS / 128, 3), 256, G_SMEM_TOTAL>>>(pa);

    attn_tc<<<dim3(SS / 128, HH, BB), 256, AT_SMEM_BYTES>>>(
        qkv, qkv + MD, qkv + 2 * MD, gh, mask, o_h);

    gemm_out<<<dim3(DD / 128, MROWS / 128), 256, G_SMEM_TOTAL>>>(
        o_h, w_h + 3 * NN, bo, out);
}